// round 4
// baseline (speedup 1.0000x reference)
#include <cuda_runtime.h>
#include <cuda_bf16.h>
#include <cstdint>
#include <math.h>

// ---------------------------------------------------------------------------
// Binarized CNN (XNOR-net) forward pass. Bit-packed XNOR-popcount convs.
//   dot = valid_taps*Cin - 2 * sum_taps popc(abits ^ wbits)
// R4: interior fast path (no bounds checks / no valid counting) for
//     interior rows+cols; checked path only on image edges. unroll-2 pixel
//     loop for MLP at low occupancy. Register weights for WW<=8.
// ---------------------------------------------------------------------------

#define NB 128

// Scratch (device globals; no allocation allowed)
__device__ uint32_t g_bits1[NB * 32 * 32 * 4];
__device__ uint32_t g_bits2[NB * 16 * 16 * 4];
__device__ uint32_t g_bits3[NB * 16 * 16 * 8];
__device__ uint32_t g_bits4[NB * 8 * 8 * 8];
__device__ uint32_t g_bits5[NB * 8 * 8 * 16];
__device__ float    g_h6[NB * 4 * 4 * 512];
__device__ uint32_t g_wb2[9 * 4 * 128];
__device__ uint32_t g_wb3[9 * 4 * 256];
__device__ uint32_t g_wb4[9 * 8 * 256];
__device__ uint32_t g_wb5[9 * 8 * 512];
__device__ uint32_t g_wb6[9 * 16 * 512];

// ---------------------------------------------------------------------------
// Fused weight-sign packing for all 5 binary layers.
// Layout per layer: [tap(9)][cin_word][cout], bit j = cin%32.
// ---------------------------------------------------------------------------
__device__ __forceinline__ void pack_one(const float* __restrict__ w,
                                         uint32_t* __restrict__ wb,
                                         int idx, int CIN, int COUT) {
    int cout = idx % COUT;
    int tw = idx / COUT;
    int cw = CIN >> 5;
    int wword = tw % cw;
    int tap = tw / cw;
    uint32_t m = 0;
#pragma unroll 8
    for (int j = 0; j < 32; j++) {
        float f = w[(tap * CIN + wword * 32 + j) * COUT + cout];
        m |= (f > 0.0f ? 1u : 0u) << j;
    }
    wb[idx] = m;
}

__global__ void pack_all_kernel(const float* __restrict__ w2, const float* __restrict__ w3,
                                const float* __restrict__ w4, const float* __restrict__ w5,
                                const float* __restrict__ w6,
                                uint32_t* __restrict__ wb2, uint32_t* __restrict__ wb3,
                                uint32_t* __restrict__ wb4, uint32_t* __restrict__ wb5,
                                uint32_t* __restrict__ wb6) {
    int idx = blockIdx.x * blockDim.x + threadIdx.x;
    const int n2 = 9 * 4 * 128, n3 = 9 * 4 * 256, n4 = 9 * 8 * 256,
              n5 = 9 * 8 * 512, n6 = 9 * 16 * 512;
    if (idx < n2) { pack_one(w2, wb2, idx, 128, 128); return; }
    idx -= n2;
    if (idx < n3) { pack_one(w3, wb3, idx, 128, 256); return; }
    idx -= n3;
    if (idx < n4) { pack_one(w4, wb4, idx, 256, 256); return; }
    idx -= n4;
    if (idx < n5) { pack_one(w5, wb5, idx, 256, 512); return; }
    idx -= n5;
    if (idx < n6) { pack_one(w6, wb6, idx, 512, 512); return; }
}

// ---------------------------------------------------------------------------
// conv1: float 3x3 SAME conv (3->128) + bias + relu + bn + binarize + pack
// ---------------------------------------------------------------------------
__global__ void conv1_kernel(const float* __restrict__ x, const float* __restrict__ w1,
                             const float* __restrict__ b1, const float* __restrict__ s1,
                             const float* __restrict__ bb1, uint32_t* __restrict__ obits) {
    int p = blockIdx.x;
    int co = threadIdx.x;
    int xx = p & 31;
    int y = (p >> 5) & 31;
    int n = p >> 10;
    float acc = 0.0f;
#pragma unroll
    for (int ky = 0; ky < 3; ky++) {
        int iy = y + ky - 1;
        if ((unsigned)iy >= 32u) continue;
#pragma unroll
        for (int kx = 0; kx < 3; kx++) {
            int ix = xx + kx - 1;
            if ((unsigned)ix >= 32u) continue;
            const float* xp = x + ((n * 32 + iy) * 32 + ix) * 3;
            const float* wp = w1 + ((ky * 3 + kx) * 3) * 128 + co;
            acc = fmaf(xp[0], wp[0], acc);
            acc = fmaf(xp[1], wp[128], acc);
            acc = fmaf(xp[2], wp[256], acc);
        }
    }
    float v = fmaxf(acc + b1[co], 0.0f);
    v = fmaf(v, s1[co], bb1[co]);
    unsigned mask = __ballot_sync(0xffffffffu, v > 0.0f);
    if ((co & 31) == 0) obits[p * 4 + (co >> 5)] = mask;
}

// ---------------------------------------------------------------------------
// Binary conv layer, compile-time shapes.
//   warp -> one output row (row = n*Ho + yo), lane -> cout = g*32 + lane.
//   WW<=8: weights in registers; WW==16: SMEM.
//   Interior rows use a checks-free dot; edge rows / edge columns use the
//   checked dot (identical integer math).
// Grid: x = N*Ho/8, y = COUT/32.
// ---------------------------------------------------------------------------

// DOT macro: defines a lambda NAME computing the binary conv dot at conv
// coords (y, x). CHECKED is a compile-time literal.
#define DOT_DEF(NAME, CHECKED)                                                 \
    auto NAME = [&](int y, int x) -> int {                                     \
        int s = 0;                                                             \
        int valid = 0;                                                         \
        _Pragma("unroll")                                                      \
        for (int ky = 0; ky < 3; ky++) {                                       \
            int iy = y + ky - 1;                                               \
            if (CHECKED && (unsigned)iy >= (unsigned)H) continue;              \
            _Pragma("unroll")                                                  \
            for (int kx = 0; kx < 3; kx++) {                                   \
                int ix = x + kx - 1;                                           \
                if (CHECKED && (unsigned)ix >= (unsigned)W) continue;          \
                valid++;                                                       \
                const uint4* ap =                                              \
                    (const uint4*)(abase + ((size_t)iy * W + ix) * WW);        \
                _Pragma("unroll")                                              \
                for (int g4 = 0; g4 < WG; g4++) {                              \
                    uint4 a = __ldg(ap + g4);                                  \
                    if constexpr (REGW) {                                      \
                        int t = (ky * 3 + kx) * WW + g4 * 4;                   \
                        s += __popc(a.x ^ wreg[t]) + __popc(a.y ^ wreg[t + 1]) \
                           + __popc(a.z ^ wreg[t + 2]) + __popc(a.w ^ wreg[t + 3]); \
                    } else {                                                   \
                        uint4 wv = sw[((ky * 3 + kx) * WG + g4) * 32 + lane];  \
                        s += __popc(a.x ^ wv.x) + __popc(a.y ^ wv.y)           \
                           + __popc(a.z ^ wv.z) + __popc(a.w ^ wv.w);          \
                    }                                                          \
                }                                                              \
            }                                                                  \
        }                                                                      \
        return (CHECKED ? valid : 9) * WW * 32 - 2 * s;                        \
    };

template <int H, int W, int WW, int COUT, bool POOL, bool FINAL>
__global__ void __launch_bounds__(256, 2) bconv_kernel(
    const uint32_t* __restrict__ abits, const uint32_t* __restrict__ wbits,
    const float* __restrict__ scale, const float* __restrict__ bias,
    uint32_t* __restrict__ obits, float* __restrict__ ofloat) {
    constexpr int Ho = POOL ? H / 2 : H;
    constexpr int Wo = POOL ? W / 2 : W;
    constexpr int WG = WW / 4;
    constexpr bool REGW = (WW <= 8);

    const int lane = threadIdx.x & 31;
    const int warp = threadIdx.x >> 5;
    const int row = blockIdx.x * 8 + warp;   // n*Ho + yo
    const int g = blockIdx.y;
    const int n = row / Ho;                  // power-of-two -> shift
    const int yo = row - n * Ho;
    const int c = g * 32 + lane;

    uint32_t wreg[REGW ? 9 * WW : 1];
    __shared__ uint4 sw[REGW ? 1 : 9 * WG * 32];
    if constexpr (REGW) {
#pragma unroll
        for (int t = 0; t < 9 * WW; t++) wreg[t] = __ldg(wbits + t * COUT + c);
    } else {
        uint32_t* sws = (uint32_t*)sw;
        for (int f = threadIdx.x; f < 9 * WW * 32; f += 256) {
            int j = f & 3;
            int ln = (f >> 2) & 31;
            int tg = f >> 7;               // tap*WG + g4
            int tap = tg / WG;
            int g4 = tg - tap * WG;
            sws[f] = wbits[(tap * WW + g4 * 4 + j) * COUT + g * 32 + ln];
        }
        __syncthreads();
    }

    const float sc = scale[c];
    const float bi = bias[c];
    const uint32_t* abase = abits + (size_t)n * H * W * WW;

    DOT_DEF(dotC, true)
    DOT_DEF(dotF, false)

    auto emit = [&](int xo, int m) {
        float val = fmaf((float)m, sc, bi);
        if constexpr (FINAL) {
            ofloat[((size_t)row * Wo + xo) * COUT + c] = val;
        } else {
            unsigned mask = __ballot_sync(0xffffffffu, val > 0.0f);
            if (lane == 0) obits[((size_t)row * Wo + xo) * (COUT / 32) + g] = mask;
        }
    };

    const bool yint = (yo >= 1) && (yo <= Ho - 2);

    if constexpr (POOL) {
        if (yint) {
            int m = 0;   // xo = 0 (checked columns)
            m = max(m, dotC(2 * yo + 0, 0)); m = max(m, dotC(2 * yo + 0, 1));
            m = max(m, dotC(2 * yo + 1, 0)); m = max(m, dotC(2 * yo + 1, 1));
            emit(0, m);
#pragma unroll 2
            for (int xo = 1; xo <= Wo - 2; xo++) {
                m = 0;
                m = max(m, dotF(2 * yo + 0, 2 * xo + 0));
                m = max(m, dotF(2 * yo + 0, 2 * xo + 1));
                m = max(m, dotF(2 * yo + 1, 2 * xo + 0));
                m = max(m, dotF(2 * yo + 1, 2 * xo + 1));
                emit(xo, m);
            }
            m = 0;       // xo = Wo-1
            m = max(m, dotC(2 * yo + 0, W - 2)); m = max(m, dotC(2 * yo + 0, W - 1));
            m = max(m, dotC(2 * yo + 1, W - 2)); m = max(m, dotC(2 * yo + 1, W - 1));
            emit(Wo - 1, m);
        } else {
#pragma unroll 1
            for (int xo = 0; xo < Wo; xo++) {
                int m = 0;
                m = max(m, dotC(2 * yo + 0, 2 * xo + 0));
                m = max(m, dotC(2 * yo + 0, 2 * xo + 1));
                m = max(m, dotC(2 * yo + 1, 2 * xo + 0));
                m = max(m, dotC(2 * yo + 1, 2 * xo + 1));
                emit(xo, m);
            }
        }
    } else {
        if (yint) {
            emit(0, max(dotC(yo, 0), 0));
#pragma unroll 2
            for (int xo = 1; xo <= W - 2; xo++) {
                emit(xo, max(dotF(yo, xo), 0));
            }
            emit(W - 1, max(dotC(yo, W - 1), 0));
        } else {
#pragma unroll 1
            for (int xo = 0; xo < W; xo++) {
                emit(xo, max(dotC(yo, xo), 0));
            }
        }
    }
}

// ---------------------------------------------------------------------------
// Dense (512->10) + softmax, one warp per output pixel.
// ---------------------------------------------------------------------------
__global__ void dense_softmax_kernel(const float* __restrict__ h, const float* __restrict__ dw,
                                     const float* __restrict__ db, float* __restrict__ out) {
    int warp = (blockIdx.x * blockDim.x + threadIdx.x) >> 5;
    int lane = threadIdx.x & 31;
    if (warp >= NB * 4 * 4) return;
    float acc[10];
#pragma unroll
    for (int j = 0; j < 10; j++) acc[j] = 0.0f;
    const float* hp = h + (size_t)warp * 512;
#pragma unroll
    for (int k = 0; k < 16; k++) {
        int cc = k * 32 + lane;
        float hv = hp[cc];
        const float* wp = dw + cc * 10;
#pragma unroll
        for (int j = 0; j < 10; j++) acc[j] = fmaf(hv, __ldg(wp + j), acc[j]);
    }
#pragma unroll
    for (int s = 16; s > 0; s >>= 1) {
#pragma unroll
        for (int j = 0; j < 10; j++) acc[j] += __shfl_xor_sync(0xffffffffu, acc[j], s);
    }
    if (lane == 0) {
        float l[10], m = -1e30f;
#pragma unroll
        for (int j = 0; j < 10; j++) { l[j] = acc[j] + db[j]; m = fmaxf(m, l[j]); }
        float sum = 0.0f;
#pragma unroll
        for (int j = 0; j < 10; j++) { l[j] = expf(l[j] - m); sum += l[j]; }
        float inv = 1.0f / sum;
#pragma unroll
        for (int j = 0; j < 10; j++) out[warp * 10 + j] = l[j] * inv;
    }
}

// ---------------------------------------------------------------------------
// Launch. Input order: 0:x 1:w1 2:b1 3:w2 4:w3 5:w4 6:w5 7:w6
//  8..19: bn{1..6}_scale/bias interleaved, 20:dense_w 21:dense_b
// ---------------------------------------------------------------------------
extern "C" void kernel_launch(void* const* d_in, const int* in_sizes, int n_in,
                              void* d_out, int out_size) {
    const float* x   = (const float*)d_in[0];
    const float* w1  = (const float*)d_in[1];
    const float* b1  = (const float*)d_in[2];
    const float* w2  = (const float*)d_in[3];
    const float* w3  = (const float*)d_in[4];
    const float* w4  = (const float*)d_in[5];
    const float* w5  = (const float*)d_in[6];
    const float* w6  = (const float*)d_in[7];
    const float* bn1s = (const float*)d_in[8];
    const float* bn1b = (const float*)d_in[9];
    const float* bn2s = (const float*)d_in[10];
    const float* bn2b = (const float*)d_in[11];
    const float* bn3s = (const float*)d_in[12];
    const float* bn3b = (const float*)d_in[13];
    const float* bn4s = (const float*)d_in[14];
    const float* bn4b = (const float*)d_in[15];
    const float* bn5s = (const float*)d_in[16];
    const float* bn5b = (const float*)d_in[17];
    const float* bn6s = (const float*)d_in[18];
    const float* bn6b = (const float*)d_in[19];
    const float* dw   = (const float*)d_in[20];
    const float* db   = (const float*)d_in[21];
    float* out = (float*)d_out;

    uint32_t *bits1, *bits2, *bits3, *bits4, *bits5;
    uint32_t *wb2, *wb3, *wb4, *wb5, *wb6;
    float* h6;
    cudaGetSymbolAddress((void**)&bits1, g_bits1);
    cudaGetSymbolAddress((void**)&bits2, g_bits2);
    cudaGetSymbolAddress((void**)&bits3, g_bits3);
    cudaGetSymbolAddress((void**)&bits4, g_bits4);
    cudaGetSymbolAddress((void**)&bits5, g_bits5);
    cudaGetSymbolAddress((void**)&wb2, g_wb2);
    cudaGetSymbolAddress((void**)&wb3, g_wb3);
    cudaGetSymbolAddress((void**)&wb4, g_wb4);
    cudaGetSymbolAddress((void**)&wb5, g_wb5);
    cudaGetSymbolAddress((void**)&wb6, g_wb6);
    cudaGetSymbolAddress((void**)&h6, g_h6);

    // 0: fused weight packing
    const int npack = 9 * 4 * 128 + 9 * 4 * 256 + 9 * 8 * 256 + 9 * 8 * 512 + 9 * 16 * 512;
    pack_all_kernel<<<(npack + 255) / 256, 256>>>(w2, w3, w4, w5, w6,
                                                  wb2, wb3, wb4, wb5, wb6);

    // 1: conv1 + relu + bn1 + binarize
    conv1_kernel<<<NB * 32 * 32, 128>>>(x, w1, b1, bn1s, bn1b, bits1);

    // 2: bconv2 (128->128) + pool + bn2      H=32 W=32 WW=4 COUT=128
    bconv_kernel<32, 32, 4, 128, true, false><<<dim3(NB * 16 / 8, 4), 256>>>(
        bits1, wb2, bn2s, bn2b, bits2, nullptr);
    // 3: bconv3 (128->256) + bn3             H=16 W=16 WW=4 COUT=256
    bconv_kernel<16, 16, 4, 256, false, false><<<dim3(NB * 16 / 8, 8), 256>>>(
        bits2, wb3, bn3s, bn3b, bits3, nullptr);
    // 4: bconv4 (256->256) + pool + bn4      H=16 W=16 WW=8 COUT=256
    bconv_kernel<16, 16, 8, 256, true, false><<<dim3(NB * 8 / 8, 8), 256>>>(
        bits3, wb4, bn4s, bn4b, bits4, nullptr);
    // 5: bconv5 (256->512) + bn5             H=8 W=8 WW=8 COUT=512  (profiled)
    bconv_kernel<8, 8, 8, 512, false, false><<<dim3(NB * 8 / 8, 16), 256>>>(
        bits4, wb5, bn5s, bn5b, bits5, nullptr);
    // 6: bconv6 (512->512) + pool + bn6 -> float   H=8 W=8 WW=16 COUT=512
    bconv_kernel<8, 8, 16, 512, true, true><<<dim3(NB * 4 / 8, 16), 256>>>(
        bits5, wb6, bn6s, bn6b, nullptr, h6);

    // 7: dense + softmax
    dense_softmax_kernel<<<NB * 4 * 4 * 32 / 256, 256>>>(h6, dw, db, out);
}

// round 6
// speedup vs baseline: 1.4713x; 1.4713x over previous
#include <cuda_runtime.h>
#include <cuda_bf16.h>
#include <cstdint>
#include <math.h>

// ---------------------------------------------------------------------------
// Binarized CNN (XNOR-net) forward pass. Bit-packed XNOR-popcount convs.
// R5/R6: lane = PIXEL mapping. Activation 3x3 patch in registers (loaded once
//     per warp-strip), weights broadcast from SMEM (uniform LDS = 1 cyc),
//     per-lane bit-word packing over the 32-cout inner loop, edge handling
//     via precomputed K-correction tables (exact integer math), maxpool via
//     shfl. bconv6 (16 cin words) runs as two cin-half passes via scratch.
// ---------------------------------------------------------------------------

#define NB 128

// Scratch (device globals; no allocation allowed)
__device__ uint32_t g_bits1[NB * 32 * 32 * 4];
__device__ uint32_t g_bits2[NB * 16 * 16 * 4];
__device__ uint32_t g_bits3[NB * 16 * 16 * 8];
__device__ uint32_t g_bits4[NB * 8 * 8 * 8];
__device__ uint32_t g_bits5[NB * 8 * 8 * 16];
__device__ float    g_h6[NB * 4 * 4 * 512];
__device__ int      g_part[NB * 8 * 8 * 512];       // bconv6 partial dots (16MB)
__device__ uint32_t g_wb2[9 * 4 * 128];
__device__ uint32_t g_wb3[9 * 4 * 256];
__device__ uint32_t g_wb4[9 * 8 * 256];
__device__ uint32_t g_wb5[9 * 8 * 512];
__device__ uint32_t g_wb6[9 * 16 * 512];
// Edge-correction tables: K[pattern(9)][cout]
__device__ int g_K2[9 * 128];
__device__ int g_K3[9 * 256];
__device__ int g_K4[9 * 256];
__device__ int g_K5[9 * 512];
__device__ int g_K6A[9 * 512];
__device__ int g_K6B[9 * 512];

// ---------------------------------------------------------------------------
// Weight-sign packing. Layout per layer: [tap(9)][cin_word][cout].
// ---------------------------------------------------------------------------
__device__ __forceinline__ void pack_one(const float* __restrict__ w,
                                         uint32_t* __restrict__ wb,
                                         int idx, int CIN, int COUT) {
    int cout = idx % COUT;
    int tw = idx / COUT;
    int cw = CIN >> 5;
    int wword = tw % cw;
    int tap = tw / cw;
    uint32_t m = 0;
#pragma unroll 8
    for (int j = 0; j < 32; j++) {
        float f = w[(tap * CIN + wword * 32 + j) * COUT + cout];
        m |= (f > 0.0f ? 1u : 0u) << j;
    }
    wb[idx] = m;
}

__global__ void pack_all_kernel(const float* __restrict__ w2, const float* __restrict__ w3,
                                const float* __restrict__ w4, const float* __restrict__ w5,
                                const float* __restrict__ w6,
                                uint32_t* __restrict__ wb2, uint32_t* __restrict__ wb3,
                                uint32_t* __restrict__ wb4, uint32_t* __restrict__ wb5,
                                uint32_t* __restrict__ wb6) {
    int idx = blockIdx.x * blockDim.x + threadIdx.x;
    const int n2 = 9 * 4 * 128, n3 = 9 * 4 * 256, n4 = 9 * 8 * 256,
              n5 = 9 * 8 * 512, n6 = 9 * 16 * 512;
    if (idx < n2) { pack_one(w2, wb2, idx, 128, 128); return; }
    idx -= n2;
    if (idx < n3) { pack_one(w3, wb3, idx, 128, 256); return; }
    idx -= n3;
    if (idx < n4) { pack_one(w4, wb4, idx, 256, 256); return; }
    idx -= n4;
    if (idx < n5) { pack_one(w5, wb5, idx, 256, 512); return; }
    idx -= n5;
    if (idx < n6) { pack_one(w6, wb6, idx, 512, 512); return; }
}

// ---------------------------------------------------------------------------
// K tables: for each (pattern p = ty*3+tx, cout):
//   K = (valid - 9)*CW*32 + 2 * sum_{invalid taps} popc(w_chunk)
// so that dot_true = 9*CW*32 - 2*S_zeropadded + K.
// ---------------------------------------------------------------------------
__device__ __forceinline__ void k_one(const uint32_t* __restrict__ wb, int* __restrict__ K,
                                      int idx, int CINW, int CW, int w0, int COUT) {
    int c = idx % COUT;
    int p = idx / COUT;
    int ty = p / 3, tx = p % 3;
    int sinv = 0, valid = 0;
    for (int ky = 0; ky < 3; ky++) {
        for (int kx = 0; kx < 3; kx++) {
            bool inv = (ty == 0 && ky == 0) || (ty == 2 && ky == 2) ||
                       (tx == 0 && kx == 0) || (tx == 2 && kx == 2);
            if (!inv) { valid++; continue; }
            for (int w = 0; w < CW; w++)
                sinv += __popc(wb[((size_t)(ky * 3 + kx) * CINW + w0 + w) * COUT + c]);
        }
    }
    K[idx] = (valid - 9) * CW * 32 + 2 * sinv;
}

__global__ void k_all_kernel(const uint32_t* __restrict__ wb2, const uint32_t* __restrict__ wb3,
                             const uint32_t* __restrict__ wb4, const uint32_t* __restrict__ wb5,
                             const uint32_t* __restrict__ wb6,
                             int* K2, int* K3, int* K4, int* K5, int* K6A, int* K6B) {
    int idx = blockIdx.x * blockDim.x + threadIdx.x;
    const int t2 = 9 * 128, t3 = 9 * 256, t4 = 9 * 256, t5 = 9 * 512, t6 = 9 * 512;
    if (idx < t2) { k_one(wb2, K2, idx, 4, 4, 0, 128); return; }
    idx -= t2;
    if (idx < t3) { k_one(wb3, K3, idx, 4, 4, 0, 256); return; }
    idx -= t3;
    if (idx < t4) { k_one(wb4, K4, idx, 8, 8, 0, 256); return; }
    idx -= t4;
    if (idx < t5) { k_one(wb5, K5, idx, 8, 8, 0, 512); return; }
    idx -= t5;
    if (idx < t6) { k_one(wb6, K6A, idx, 16, 8, 0, 512); return; }
    idx -= t6;
    if (idx < t6) { k_one(wb6, K6B, idx, 16, 8, 8, 512); return; }
}

// ---------------------------------------------------------------------------
// conv1: float 3x3 SAME conv (3->128) + bias + relu + bn + binarize + pack
// ---------------------------------------------------------------------------
__global__ void conv1_kernel(const float* __restrict__ x, const float* __restrict__ w1,
                             const float* __restrict__ b1, const float* __restrict__ s1,
                             const float* __restrict__ bb1, uint32_t* __restrict__ obits) {
    int p = blockIdx.x;
    int co = threadIdx.x;
    int xx = p & 31;
    int y = (p >> 5) & 31;
    int n = p >> 10;
    float acc = 0.0f;
#pragma unroll
    for (int ky = 0; ky < 3; ky++) {
        int iy = y + ky - 1;
        if ((unsigned)iy >= 32u) continue;
#pragma unroll
        for (int kx = 0; kx < 3; kx++) {
            int ix = xx + kx - 1;
            if ((unsigned)ix >= 32u) continue;
            const float* xp = x + ((n * 32 + iy) * 32 + ix) * 3;
            const float* wp = w1 + ((ky * 3 + kx) * 3) * 128 + co;
            acc = fmaf(xp[0], wp[0], acc);
            acc = fmaf(xp[1], wp[128], acc);
            acc = fmaf(xp[2], wp[256], acc);
        }
    }
    float v = fmaxf(acc + b1[co], 0.0f);
    v = fmaf(v, s1[co], bb1[co]);
    unsigned mask = __ballot_sync(0xffffffffu, v > 0.0f);
    if ((co & 31) == 0) obits[p * 4 + (co >> 5)] = mask;
}

// ---------------------------------------------------------------------------
// Binary conv, lane = pixel.
//   H,W: pre-pool spatial. CINW: input words/pixel. CW: words this pass.
//   W0: word offset of this pass. COUT: output channels.
//   MODE: 0 = binarize->bits out, 1 = store partial int dots, 2 = final
//         float out, adding stored partials.
// Warp strip: RS rows x CS cols (CS = min(W,16), RS = 32/CS).
// Grid: x = (NB*H*W/32)/4 blocks of 4 warps, y = COUT/32.
// ---------------------------------------------------------------------------
template <int H, int W, int CINW, int CW, int W0, int COUT, bool POOL, int MODE>
__global__ void __launch_bounds__(128) bconv_px(
    const uint32_t* __restrict__ abits, const uint32_t* __restrict__ wbits,
    const int* __restrict__ Ktab, const float* __restrict__ scale,
    const float* __restrict__ bias, uint32_t* __restrict__ obits,
    int* __restrict__ part, float* __restrict__ ofloat) {
    constexpr int CS = (W < 16) ? W : 16;
    constexpr int RS = 32 / CS;
    constexpr int SPI = (H * W) / 32;       // strips per image
    constexpr int WCS = W / CS;             // col-strips per row-group
    constexpr int TPW = 9 * CW / 4;         // uint4 per cout
    constexpr int NPIX = NB * H * W;

    __shared__ uint4 sw4[32 * TPW];
    __shared__ int sk[9 * 33];
    __shared__ float ssc[32], sbi[32];

    const int g = blockIdx.y;
    {
        uint32_t* sws = (uint32_t*)sw4;
        for (int idx = threadIdx.x; idx < 32 * 9 * CW; idx += 128) {
            int c = idx / (9 * CW);
            int t = idx - c * (9 * CW);
            int tap = t / CW, w = t - tap * CW;
            sws[idx] = wbits[((size_t)tap * CINW + W0 + w) * COUT + g * 32 + c];
        }
        for (int idx = threadIdx.x; idx < 9 * 32; idx += 128) {
            int p = idx >> 5, c = idx & 31;
            sk[p * 33 + c] = Ktab[p * COUT + g * 32 + c];
        }
        if (threadIdx.x < 32) {
            ssc[threadIdx.x] = scale[g * 32 + threadIdx.x];
            sbi[threadIdx.x] = bias[g * 32 + threadIdx.x];
        }
    }
    __syncthreads();

    const int lane = threadIdx.x & 31;
    const int warp = threadIdx.x >> 5;
    const int sid = blockIdx.x * 4 + warp;
    const int n = sid / SPI;
    const int si = sid - n * SPI;
    const int rowg = si / WCS;
    const int colg = si - rowg * WCS;
    const int r = lane / CS;
    const int x = lane - r * CS;
    const int py = rowg * RS + r;
    const int px = colg * CS + x;

    // Activation patch (zero-filled outside the image)
    uint4 patch[TPW];
#pragma unroll
    for (int ky = 0; ky < 3; ky++) {
#pragma unroll
        for (int kx = 0; kx < 3; kx++) {
            int iy = py + ky - 1, ix = px + kx - 1;
            bool ok = ((unsigned)iy < (unsigned)H) && ((unsigned)ix < (unsigned)W);
            const uint4* ap =
                (const uint4*)(abits + ((size_t)(n * H + iy) * W + ix) * CINW + W0);
#pragma unroll
            for (int q = 0; q < CW / 4; q++) {
                uint4 a = make_uint4(0u, 0u, 0u, 0u);
                if (ok) a = __ldg(ap + q);
                patch[(ky * 3 + kx) * (CW / 4) + q] = a;
            }
        }
    }

    const int ty = (py == 0) ? 0 : ((py == H - 1) ? 2 : 1);
    const int txp = (px == 0) ? 0 : ((px == W - 1) ? 2 : 1);
    const int pat = ty * 3 + txp;
    const int gpix = (n * H + py) * W + px;

    uint32_t word = 0;
#pragma unroll 1
    for (int c = 0; c < 32; c++) {
        const uint4* wr = &sw4[c * TPW];
        int s = 0;
#pragma unroll
        for (int t = 0; t < TPW; t++) {
            uint4 wv = wr[t];          // warp-uniform address -> LDS broadcast
            uint4 av = patch[t];
            s += __popc(av.x ^ wv.x) + __popc(av.y ^ wv.y) +
                 __popc(av.z ^ wv.z) + __popc(av.w ^ wv.w);
        }
        int dot = 9 * CW * 32 - 2 * s + sk[pat * 33 + c];

        if constexpr (MODE == 1) {
            part[(size_t)(g * 32 + c) * NPIX + gpix] = dot;
        } else {
            int m = dot;
            if constexpr (MODE == 2)
                m += __ldg(part + (size_t)(g * 32 + c) * NPIX + gpix);
            m = max(m, 0);                       // relu (before pool is exact)
            if constexpr (POOL) {
                m = max(m, __shfl_xor_sync(0xffffffffu, m, 1));
                m = max(m, __shfl_xor_sync(0xffffffffu, m, CS));
            }
            float v = fmaf((float)m, ssc[c], sbi[c]);
            if constexpr (MODE == 2) {
                if (((r & 1) == 0) && ((x & 1) == 0)) {
                    int opix = (n * (H / 2) + (py >> 1)) * (W / 2) + (px >> 1);
                    ofloat[(size_t)opix * COUT + g * 32 + c] = v;
                }
            } else {
                word |= (v > 0.0f ? 1u : 0u) << c;
            }
        }
    }

    if constexpr (MODE == 0) {
        if constexpr (POOL) {
            if (((r & 1) == 0) && ((x & 1) == 0)) {
                int opix = (n * (H / 2) + (py >> 1)) * (W / 2) + (px >> 1);
                obits[(size_t)opix * (COUT / 32) + g] = word;
            }
        } else {
            obits[(size_t)gpix * (COUT / 32) + g] = word;
        }
    }
}

// ---------------------------------------------------------------------------
// Dense (512->10) + softmax, one warp per output pixel.
// ---------------------------------------------------------------------------
__global__ void dense_softmax_kernel(const float* __restrict__ h, const float* __restrict__ dw,
                                     const float* __restrict__ db, float* __restrict__ out) {
    int warp = (blockIdx.x * blockDim.x + threadIdx.x) >> 5;
    int lane = threadIdx.x & 31;
    if (warp >= NB * 4 * 4) return;
    float acc[10];
#pragma unroll
    for (int j = 0; j < 10; j++) acc[j] = 0.0f;
    const float* hp = h + (size_t)warp * 512;
#pragma unroll
    for (int k = 0; k < 16; k++) {
        int cc = k * 32 + lane;
        float hv = hp[cc];
        const float* wp = dw + cc * 10;
#pragma unroll
        for (int j = 0; j < 10; j++) acc[j] = fmaf(hv, __ldg(wp + j), acc[j]);
    }
#pragma unroll
    for (int s = 16; s > 0; s >>= 1) {
#pragma unroll
        for (int j = 0; j < 10; j++) acc[j] += __shfl_xor_sync(0xffffffffu, acc[j], s);
    }
    if (lane == 0) {
        float l[10], m = -1e30f;
#pragma unroll
        for (int j = 0; j < 10; j++) { l[j] = acc[j] + db[j]; m = fmaxf(m, l[j]); }
        float sum = 0.0f;
#pragma unroll
        for (int j = 0; j < 10; j++) { l[j] = expf(l[j] - m); sum += l[j]; }
        float inv = 1.0f / sum;
#pragma unroll
        for (int j = 0; j < 10; j++) out[warp * 10 + j] = l[j] * inv;
    }
}

// ---------------------------------------------------------------------------
// Launch. Input order: 0:x 1:w1 2:b1 3:w2 4:w3 5:w4 6:w5 7:w6
//  8..19: bn{1..6}_scale/bias interleaved, 20:dense_w 21:dense_b
// ---------------------------------------------------------------------------
extern "C" void kernel_launch(void* const* d_in, const int* in_sizes, int n_in,
                              void* d_out, int out_size) {
    const float* x   = (const float*)d_in[0];
    const float* w1  = (const float*)d_in[1];
    const float* b1  = (const float*)d_in[2];
    const float* w2  = (const float*)d_in[3];
    const float* w3  = (const float*)d_in[4];
    const float* w4  = (const float*)d_in[5];
    const float* w5  = (const float*)d_in[6];
    const float* w6  = (const float*)d_in[7];
    const float* bn1s = (const float*)d_in[8];
    const float* bn1b = (const float*)d_in[9];
    const float* bn2s = (const float*)d_in[10];
    const float* bn2b = (const float*)d_in[11];
    const float* bn3s = (const float*)d_in[12];
    const float* bn3b = (const float*)d_in[13];
    const float* bn4s = (const float*)d_in[14];
    const float* bn4b = (const float*)d_in[15];
    const float* bn5s = (const float*)d_in[16];
    const float* bn5b = (const float*)d_in[17];
    const float* bn6s = (const float*)d_in[18];
    const float* bn6b = (const float*)d_in[19];
    const float* dw   = (const float*)d_in[20];
    const float* db   = (const float*)d_in[21];
    float* out = (float*)d_out;

    uint32_t *bits1, *bits2, *bits3, *bits4, *bits5;
    uint32_t *wb2, *wb3, *wb4, *wb5, *wb6;
    int *K2, *K3, *K4, *K5, *K6A, *K6B, *part;
    float* h6;
    cudaGetSymbolAddress((void**)&bits1, g_bits1);
    cudaGetSymbolAddress((void**)&bits2, g_bits2);
    cudaGetSymbolAddress((void**)&bits3, g_bits3);
    cudaGetSymbolAddress((void**)&bits4, g_bits4);
    cudaGetSymbolAddress((void**)&bits5, g_bits5);
    cudaGetSymbolAddress((void**)&wb2, g_wb2);
    cudaGetSymbolAddress((void**)&wb3, g_wb3);
    cudaGetSymbolAddress((void**)&wb4, g_wb4);
    cudaGetSymbolAddress((void**)&wb5, g_wb5);
    cudaGetSymbolAddress((void**)&wb6, g_wb6);
    cudaGetSymbolAddress((void**)&K2, g_K2);
    cudaGetSymbolAddress((void**)&K3, g_K3);
    cudaGetSymbolAddress((void**)&K4, g_K4);
    cudaGetSymbolAddress((void**)&K5, g_K5);
    cudaGetSymbolAddress((void**)&K6A, g_K6A);
    cudaGetSymbolAddress((void**)&K6B, g_K6B);
    cudaGetSymbolAddress((void**)&part, g_part);
    cudaGetSymbolAddress((void**)&h6, g_h6);

    // 0: weight packing
    const int npack = 9 * 4 * 128 + 9 * 4 * 256 + 9 * 8 * 256 + 9 * 8 * 512 + 9 * 16 * 512;
    pack_all_kernel<<<(npack + 255) / 256, 256>>>(w2, w3, w4, w5, w6,
                                                  wb2, wb3, wb4, wb5, wb6);
    // 1: K tables
    const int nk = 9 * (128 + 256 + 256 + 512 + 512 + 512);
    k_all_kernel<<<(nk + 255) / 256, 256>>>(wb2, wb3, wb4, wb5, wb6,
                                            K2, K3, K4, K5, K6A, K6B);

    // 2: conv1 + relu + bn1 + binarize
    conv1_kernel<<<NB * 32 * 32, 128>>>(x, w1, b1, bn1s, bn1b, bits1);

    // 3: bconv2 (128->128) + pool + bn2   strips = 128*32 = 4096
    bconv_px<32, 32, 4, 4, 0, 128, true, 0><<<dim3(1024, 4), 128>>>(
        bits1, wb2, K2, bn2s, bn2b, bits2, nullptr, nullptr);
    // 4: bconv3 (128->256) + bn3          strips = 128*8 = 1024
    bconv_px<16, 16, 4, 4, 0, 256, false, 0><<<dim3(256, 8), 128>>>(
        bits2, wb3, K3, bn3s, bn3b, bits3, nullptr, nullptr);
    // 5: bconv4 (256->256) + pool + bn4   (profiled slot)
    bconv_px<16, 16, 8, 8, 0, 256, true, 0><<<dim3(256, 8), 128>>>(
        bits3, wb4, K4, bn4s, bn4b, bits4, nullptr, nullptr);
    // 6: bconv5 (256->512) + bn5          strips = 128*2 = 256
    bconv_px<8, 8, 8, 8, 0, 512, false, 0><<<dim3(64, 16), 128>>>(
        bits4, wb5, K5, bn5s, bn5b, bits5, nullptr, nullptr);
    // 7: bconv6 pass A (cin words 0..7) -> partial dots
    bconv_px<8, 8, 16, 8, 0, 512, false, 1><<<dim3(64, 16), 128>>>(
        bits5, wb6, K6A, bn6s, bn6b, nullptr, part, nullptr);
    // 8: bconv6 pass B (cin words 8..15) + partial + relu + pool + bn6 -> h6
    bconv_px<8, 8, 16, 8, 8, 512, true, 2><<<dim3(64, 16), 128>>>(
        bits5, wb6, K6B, bn6s, bn6b, nullptr, part, h6);

    // 9: dense + softmax
    dense_softmax_kernel<<<NB * 4 * 4 * 32 / 256, 256>>>(h6, dw, db, out);
}

// round 8
// speedup vs baseline: 1.8432x; 1.2528x over previous
#include <cuda_runtime.h>
#include <cuda_bf16.h>
#include <cstdint>
#include <math.h>

// ---------------------------------------------------------------------------
// Binarized CNN (XNOR-net) forward pass. Bit-packed XNOR-popcount convs.
// R7/R8: CSA (carry-save) compression of the XOR'd words before popcount.
//     POPC on sm_103a is ~quarter-rate; LOP3 is full-rate. Two CSA levels
//     turn 36 POPCs into 16 POPCs + 32 LOP3s per dot block (exact integer
//     math). Rest identical to the verified R6 kernel: lane=pixel mapping,
//     broadcast SMEM weights, K-correction edge tables, shfl maxpool,
//     bconv6 as two cin-half passes.
// ---------------------------------------------------------------------------

#define NB 128

// Scratch (device globals; no allocation allowed)
__device__ uint32_t g_bits1[NB * 32 * 32 * 4];
__device__ uint32_t g_bits2[NB * 16 * 16 * 4];
__device__ uint32_t g_bits3[NB * 16 * 16 * 8];
__device__ uint32_t g_bits4[NB * 8 * 8 * 8];
__device__ uint32_t g_bits5[NB * 8 * 8 * 16];
__device__ float    g_h6[NB * 4 * 4 * 512];
__device__ int      g_part[NB * 8 * 8 * 512];       // bconv6 partial dots
__device__ uint32_t g_wb2[9 * 4 * 128];
__device__ uint32_t g_wb3[9 * 4 * 256];
__device__ uint32_t g_wb4[9 * 8 * 256];
__device__ uint32_t g_wb5[9 * 8 * 512];
__device__ uint32_t g_wb6[9 * 16 * 512];
// Edge-correction tables: K[pattern(9)][cout]
__device__ int g_K2[9 * 128];
__device__ int g_K3[9 * 256];
__device__ int g_K4[9 * 256];
__device__ int g_K5[9 * 512];
__device__ int g_K6A[9 * 512];
__device__ int g_K6B[9 * 512];

// ---------------------------------------------------------------------------
// Weight-sign packing. Layout per layer: [tap(9)][cin_word][cout].
// ---------------------------------------------------------------------------
__device__ __forceinline__ void pack_one(const float* __restrict__ w,
                                         uint32_t* __restrict__ wb,
                                         int idx, int CIN, int COUT) {
    int cout = idx % COUT;
    int tw = idx / COUT;
    int cw = CIN >> 5;
    int wword = tw % cw;
    int tap = tw / cw;
    uint32_t m = 0;
#pragma unroll 8
    for (int j = 0; j < 32; j++) {
        float f = w[(tap * CIN + wword * 32 + j) * COUT + cout];
        m |= (f > 0.0f ? 1u : 0u) << j;
    }
    wb[idx] = m;
}

__global__ void pack_all_kernel(const float* __restrict__ w2, const float* __restrict__ w3,
                                const float* __restrict__ w4, const float* __restrict__ w5,
                                const float* __restrict__ w6,
                                uint32_t* __restrict__ wb2, uint32_t* __restrict__ wb3,
                                uint32_t* __restrict__ wb4, uint32_t* __restrict__ wb5,
                                uint32_t* __restrict__ wb6) {
    int idx = blockIdx.x * blockDim.x + threadIdx.x;
    const int n2 = 9 * 4 * 128, n3 = 9 * 4 * 256, n4 = 9 * 8 * 256,
              n5 = 9 * 8 * 512, n6 = 9 * 16 * 512;
    if (idx < n2) { pack_one(w2, wb2, idx, 128, 128); return; }
    idx -= n2;
    if (idx < n3) { pack_one(w3, wb3, idx, 128, 256); return; }
    idx -= n3;
    if (idx < n4) { pack_one(w4, wb4, idx, 256, 256); return; }
    idx -= n4;
    if (idx < n5) { pack_one(w5, wb5, idx, 256, 512); return; }
    idx -= n5;
    if (idx < n6) { pack_one(w6, wb6, idx, 512, 512); return; }
}

// ---------------------------------------------------------------------------
// K tables: K = (valid - 9)*CW*32 + 2 * sum_{invalid taps} popc(w_chunk)
// so that dot_true = 9*CW*32 - 2*S_zeropadded + K.
// ---------------------------------------------------------------------------
__device__ __forceinline__ void k_one(const uint32_t* __restrict__ wb, int* __restrict__ K,
                                      int idx, int CINW, int CW, int w0, int COUT) {
    int c = idx % COUT;
    int p = idx / COUT;
    int ty = p / 3, tx = p % 3;
    int sinv = 0, valid = 0;
    for (int ky = 0; ky < 3; ky++) {
        for (int kx = 0; kx < 3; kx++) {
            bool inv = (ty == 0 && ky == 0) || (ty == 2 && ky == 2) ||
                       (tx == 0 && kx == 0) || (tx == 2 && kx == 2);
            if (!inv) { valid++; continue; }
            for (int w = 0; w < CW; w++)
                sinv += __popc(wb[((size_t)(ky * 3 + kx) * CINW + w0 + w) * COUT + c]);
        }
    }
    K[idx] = (valid - 9) * CW * 32 + 2 * sinv;
}

__global__ void k_all_kernel(const uint32_t* __restrict__ wb2, const uint32_t* __restrict__ wb3,
                             const uint32_t* __restrict__ wb4, const uint32_t* __restrict__ wb5,
                             const uint32_t* __restrict__ wb6,
                             int* K2, int* K3, int* K4, int* K5, int* K6A, int* K6B) {
    int idx = blockIdx.x * blockDim.x + threadIdx.x;
    const int t2 = 9 * 128, t3 = 9 * 256, t4 = 9 * 256, t5 = 9 * 512, t6 = 9 * 512;
    if (idx < t2) { k_one(wb2, K2, idx, 4, 4, 0, 128); return; }
    idx -= t2;
    if (idx < t3) { k_one(wb3, K3, idx, 4, 4, 0, 256); return; }
    idx -= t3;
    if (idx < t4) { k_one(wb4, K4, idx, 8, 8, 0, 256); return; }
    idx -= t4;
    if (idx < t5) { k_one(wb5, K5, idx, 8, 8, 0, 512); return; }
    idx -= t5;
    if (idx < t6) { k_one(wb6, K6A, idx, 16, 8, 0, 512); return; }
    idx -= t6;
    if (idx < t6) { k_one(wb6, K6B, idx, 16, 8, 8, 512); return; }
}

// ---------------------------------------------------------------------------
// conv1: float 3x3 SAME conv (3->128) + bias + relu + bn + binarize + pack
// ---------------------------------------------------------------------------
__global__ void conv1_kernel(const float* __restrict__ x, const float* __restrict__ w1,
                             const float* __restrict__ b1, const float* __restrict__ s1,
                             const float* __restrict__ bb1, uint32_t* __restrict__ obits) {
    int p = blockIdx.x;
    int co = threadIdx.x;
    int xx = p & 31;
    int y = (p >> 5) & 31;
    int n = p >> 10;
    float acc = 0.0f;
#pragma unroll
    for (int ky = 0; ky < 3; ky++) {
        int iy = y + ky - 1;
        if ((unsigned)iy >= 32u) continue;
#pragma unroll
        for (int kx = 0; kx < 3; kx++) {
            int ix = xx + kx - 1;
            if ((unsigned)ix >= 32u) continue;
            const float* xp = x + ((n * 32 + iy) * 32 + ix) * 3;
            const float* wp = w1 + ((ky * 3 + kx) * 3) * 128 + co;
            acc = fmaf(xp[0], wp[0], acc);
            acc = fmaf(xp[1], wp[128], acc);
            acc = fmaf(xp[2], wp[256], acc);
        }
    }
    float v = fmaxf(acc + b1[co], 0.0f);
    v = fmaf(v, s1[co], bb1[co]);
    unsigned mask = __ballot_sync(0xffffffffu, v > 0.0f);
    if ((co & 31) == 0) obits[p * 4 + (co >> 5)] = mask;
}

// Full adder (carry-save): s = xor3 (LOP3 0x96), c = majority (LOP3 0xE8).
__device__ __forceinline__ void csa(uint32_t a, uint32_t b, uint32_t d,
                                    uint32_t& s, uint32_t& c) {
    s = a ^ b ^ d;
    c = (a & b) | (d & (a ^ b));
}

// ---------------------------------------------------------------------------
// Binary conv, lane = pixel, CSA-compressed popcount.
//   MODE: 0 = binarize->bits out, 1 = store partial int dots, 2 = final
//         float out, adding stored partials.
// Warp strip: RS rows x CS cols (CS = min(W,16), RS = 32/CS).
// Grid: x = (NB*H*W/32)/4 blocks of 4 warps, y = COUT/32.
// ---------------------------------------------------------------------------
template <int H, int W, int CINW, int CW, int W0, int COUT, bool POOL, int MODE>
__global__ void __launch_bounds__(128) bconv_px(
    const uint32_t* __restrict__ abits, const uint32_t* __restrict__ wbits,
    const int* __restrict__ Ktab, const float* __restrict__ scale,
    const float* __restrict__ bias, uint32_t* __restrict__ obits,
    int* __restrict__ part, float* __restrict__ ofloat) {
    constexpr int CS = (W < 16) ? W : 16;
    constexpr int RS = 32 / CS;
    constexpr int SPI = (H * W) / 32;       // strips per image
    constexpr int WCS = W / CS;             // col-strips per row-group
    constexpr int TPW = 9 * CW / 4;         // uint4 per cout
    constexpr int NBLK = (9 * CW) / 36;     // 36-word CSA blocks (CW=4 ->1, 8 ->2)
    constexpr int NPIX = NB * H * W;

    __shared__ uint4 sw4[32 * TPW];
    __shared__ int sk[9 * 33];
    __shared__ float ssc[32], sbi[32];

    const int g = blockIdx.y;
    {
        uint32_t* sws = (uint32_t*)sw4;
        for (int idx = threadIdx.x; idx < 32 * 9 * CW; idx += 128) {
            int c = idx / (9 * CW);
            int t = idx - c * (9 * CW);
            int tap = t / CW, w = t - tap * CW;
            sws[idx] = wbits[((size_t)tap * CINW + W0 + w) * COUT + g * 32 + c];
        }
        for (int idx = threadIdx.x; idx < 9 * 32; idx += 128) {
            int p = idx >> 5, c = idx & 31;
            sk[p * 33 + c] = Ktab[p * COUT + g * 32 + c];
        }
        if (threadIdx.x < 32) {
            ssc[threadIdx.x] = scale[g * 32 + threadIdx.x];
            sbi[threadIdx.x] = bias[g * 32 + threadIdx.x];
        }
    }
    __syncthreads();

    const int lane = threadIdx.x & 31;
    const int warp = threadIdx.x >> 5;
    const int sid = blockIdx.x * 4 + warp;
    const int n = sid / SPI;
    const int si = sid - n * SPI;
    const int rowg = si / WCS;
    const int colg = si - rowg * WCS;
    const int r = lane / CS;
    const int x = lane - r * CS;
    const int py = rowg * RS + r;
    const int px = colg * CS + x;

    // Activation patch (zero-filled outside the image)
    uint4 patch[TPW];
#pragma unroll
    for (int ky = 0; ky < 3; ky++) {
#pragma unroll
        for (int kx = 0; kx < 3; kx++) {
            int iy = py + ky - 1, ix = px + kx - 1;
            bool ok = ((unsigned)iy < (unsigned)H) && ((unsigned)ix < (unsigned)W);
            const uint4* ap =
                (const uint4*)(abits + ((size_t)(n * H + iy) * W + ix) * CINW + W0);
#pragma unroll
            for (int q = 0; q < CW / 4; q++) {
                uint4 a = make_uint4(0u, 0u, 0u, 0u);
                if (ok) a = __ldg(ap + q);
                patch[(ky * 3 + kx) * (CW / 4) + q] = a;
            }
        }
    }

    const int ty = (py == 0) ? 0 : ((py == H - 1) ? 2 : 1);
    const int txp = (px == 0) ? 0 : ((px == W - 1) ? 2 : 1);
    const int pat = ty * 3 + txp;
    const int gpix = (n * H + py) * W + px;

    uint32_t word = 0;
#pragma unroll 1
    for (int c = 0; c < 32; c++) {
        const uint4* wr = &sw4[c * TPW];
        int s = 0;
#pragma unroll
        for (int blk = 0; blk < NBLK; blk++) {
            // XOR 36 words
            uint32_t xw[36];
#pragma unroll
            for (int t = 0; t < 9; t++) {
                uint4 wv = wr[blk * 9 + t];      // warp-uniform -> LDS broadcast
                uint4 av = patch[blk * 9 + t];
                xw[t * 4 + 0] = av.x ^ wv.x;
                xw[t * 4 + 1] = av.y ^ wv.y;
                xw[t * 4 + 2] = av.z ^ wv.z;
                xw[t * 4 + 3] = av.w ^ wv.w;
            }
            // CSA level 1: 36 -> 12 s1 (wt1) + 12 c1 (wt2)
            uint32_t s1[12], c1[12];
#pragma unroll
            for (int i = 0; i < 12; i++)
                csa(xw[3 * i], xw[3 * i + 1], xw[3 * i + 2], s1[i], c1[i]);
            // CSA level 2: 12 s1 -> 4 s2 (wt1) + 4 c2 (wt2);
            //              12 c1 -> 4 t2 (wt2) + 4 d4 (wt4)
            uint32_t s2[4], c2[4], t2[4], d4[4];
#pragma unroll
            for (int i = 0; i < 4; i++)
                csa(s1[3 * i], s1[3 * i + 1], s1[3 * i + 2], s2[i], c2[i]);
#pragma unroll
            for (int i = 0; i < 4; i++)
                csa(c1[3 * i], c1[3 * i + 1], c1[3 * i + 2], t2[i], d4[i]);
            int A = __popc(s2[0]) + __popc(s2[1]) + __popc(s2[2]) + __popc(s2[3]);
            int B = __popc(c2[0]) + __popc(c2[1]) + __popc(c2[2]) + __popc(c2[3]) +
                    __popc(t2[0]) + __popc(t2[1]) + __popc(t2[2]) + __popc(t2[3]);
            int C = __popc(d4[0]) + __popc(d4[1]) + __popc(d4[2]) + __popc(d4[3]);
            s += A + 2 * (B + 2 * C);       // exact popcount sum of the 36 words
        }
        int dot = 9 * CW * 32 - 2 * s + sk[pat * 33 + c];

        if constexpr (MODE == 1) {
            part[(size_t)(g * 32 + c) * NPIX + gpix] = dot;
        } else {
            int m = dot;
            if constexpr (MODE == 2)
                m += __ldg(part + (size_t)(g * 32 + c) * NPIX + gpix);
            m = max(m, 0);                       // relu (before pool is exact)
            if constexpr (POOL) {
                m = max(m, __shfl_xor_sync(0xffffffffu, m, 1));
                m = max(m, __shfl_xor_sync(0xffffffffu, m, CS));
            }
            float v = fmaf((float)m, ssc[c], sbi[c]);
            if constexpr (MODE == 2) {
                if (((r & 1) == 0) && ((x & 1) == 0)) {
                    int opix = (n * (H / 2) + (py >> 1)) * (W / 2) + (px >> 1);
                    ofloat[(size_t)opix * COUT + g * 32 + c] = v;
                }
            } else {
                word |= (v > 0.0f ? 1u : 0u) << c;
            }
        }
    }

    if constexpr (MODE == 0) {
        if constexpr (POOL) {
            if (((r & 1) == 0) && ((x & 1) == 0)) {
                int opix = (n * (H / 2) + (py >> 1)) * (W / 2) + (px >> 1);
                obits[(size_t)opix * (COUT / 32) + g] = word;
            }
        } else {
            obits[(size_t)gpix * (COUT / 32) + g] = word;
        }
    }
}

// ---------------------------------------------------------------------------
// Dense (512->10) + softmax, one warp per output pixel.
// ---------------------------------------------------------------------------
__global__ void dense_softmax_kernel(const float* __restrict__ h, const float* __restrict__ dw,
                                     const float* __restrict__ db, float* __restrict__ out) {
    int warp = (blockIdx.x * blockDim.x + threadIdx.x) >> 5;
    int lane = threadIdx.x & 31;
    if (warp >= NB * 4 * 4) return;
    float acc[10];
#pragma unroll
    for (int j = 0; j < 10; j++) acc[j] = 0.0f;
    const float* hp = h + (size_t)warp * 512;
#pragma unroll
    for (int k = 0; k < 16; k++) {
        int cc = k * 32 + lane;
        float hv = hp[cc];
        const float* wp = dw + cc * 10;
#pragma unroll
        for (int j = 0; j < 10; j++) acc[j] = fmaf(hv, __ldg(wp + j), acc[j]);
    }
#pragma unroll
    for (int s = 16; s > 0; s >>= 1) {
#pragma unroll
        for (int j = 0; j < 10; j++) acc[j] += __shfl_xor_sync(0xffffffffu, acc[j], s);
    }
    if (lane == 0) {
        float l[10], m = -1e30f;
#pragma unroll
        for (int j = 0; j < 10; j++) { l[j] = acc[j] + db[j]; m = fmaxf(m, l[j]); }
        float sum = 0.0f;
#pragma unroll
        for (int j = 0; j < 10; j++) { l[j] = expf(l[j] - m); sum += l[j]; }
        float inv = 1.0f / sum;
#pragma unroll
        for (int j = 0; j < 10; j++) out[warp * 10 + j] = l[j] * inv;
    }
}

// ---------------------------------------------------------------------------
// Launch. Input order: 0:x 1:w1 2:b1 3:w2 4:w3 5:w4 6:w5 7:w6
//  8..19: bn{1..6}_scale/bias interleaved, 20:dense_w 21:dense_b
// ---------------------------------------------------------------------------
extern "C" void kernel_launch(void* const* d_in, const int* in_sizes, int n_in,
                              void* d_out, int out_size) {
    const float* x   = (const float*)d_in[0];
    const float* w1  = (const float*)d_in[1];
    const float* b1  = (const float*)d_in[2];
    const float* w2  = (const float*)d_in[3];
    const float* w3  = (const float*)d_in[4];
    const float* w4  = (const float*)d_in[5];
    const float* w5  = (const float*)d_in[6];
    const float* w6  = (const float*)d_in[7];
    const float* bn1s = (const float*)d_in[8];
    const float* bn1b = (const float*)d_in[9];
    const float* bn2s = (const float*)d_in[10];
    const float* bn2b = (const float*)d_in[11];
    const float* bn3s = (const float*)d_in[12];
    const float* bn3b = (const float*)d_in[13];
    const float* bn4s = (const float*)d_in[14];
    const float* bn4b = (const float*)d_in[15];
    const float* bn5s = (const float*)d_in[16];
    const float* bn5b = (const float*)d_in[17];
    const float* bn6s = (const float*)d_in[18];
    const float* bn6b = (const float*)d_in[19];
    const float* dw   = (const float*)d_in[20];
    const float* db   = (const float*)d_in[21];
    float* out = (float*)d_out;

    uint32_t *bits1, *bits2, *bits3, *bits4, *bits5;
    uint32_t *wb2, *wb3, *wb4, *wb5, *wb6;
    int *K2, *K3, *K4, *K5, *K6A, *K6B, *part;
    float* h6;
    cudaGetSymbolAddress((void**)&bits1, g_bits1);
    cudaGetSymbolAddress((void**)&bits2, g_bits2);
    cudaGetSymbolAddress((void**)&bits3, g_bits3);
    cudaGetSymbolAddress((void**)&bits4, g_bits4);
    cudaGetSymbolAddress((void**)&bits5, g_bits5);
    cudaGetSymbolAddress((void**)&wb2, g_wb2);
    cudaGetSymbolAddress((void**)&wb3, g_wb3);
    cudaGetSymbolAddress((void**)&wb4, g_wb4);
    cudaGetSymbolAddress((void**)&wb5, g_wb5);
    cudaGetSymbolAddress((void**)&wb6, g_wb6);
    cudaGetSymbolAddress((void**)&K2, g_K2);
    cudaGetSymbolAddress((void**)&K3, g_K3);
    cudaGetSymbolAddress((void**)&K4, g_K4);
    cudaGetSymbolAddress((void**)&K5, g_K5);
    cudaGetSymbolAddress((void**)&K6A, g_K6A);
    cudaGetSymbolAddress((void**)&K6B, g_K6B);
    cudaGetSymbolAddress((void**)&part, g_part);
    cudaGetSymbolAddress((void**)&h6, g_h6);

    // 0: weight packing
    const int npack = 9 * 4 * 128 + 9 * 4 * 256 + 9 * 8 * 256 + 9 * 8 * 512 + 9 * 16 * 512;
    pack_all_kernel<<<(npack + 255) / 256, 256>>>(w2, w3, w4, w5, w6,
                                                  wb2, wb3, wb4, wb5, wb6);
    // 1: K tables
    const int nk = 9 * (128 + 256 + 256 + 512 + 512 + 512);
    k_all_kernel<<<(nk + 255) / 256, 256>>>(wb2, wb3, wb4, wb5, wb6,
                                            K2, K3, K4, K5, K6A, K6B);

    // 2: conv1 + relu + bn1 + binarize
    conv1_kernel<<<NB * 32 * 32, 128>>>(x, w1, b1, bn1s, bn1b, bits1);

    // 3: bconv2 (128->128) + pool + bn2
    bconv_px<32, 32, 4, 4, 0, 128, true, 0><<<dim3(1024, 4), 128>>>(
        bits1, wb2, K2, bn2s, bn2b, bits2, nullptr, nullptr);
    // 4: bconv3 (128->256) + bn3
    bconv_px<16, 16, 4, 4, 0, 256, false, 0><<<dim3(256, 8), 128>>>(
        bits2, wb3, K3, bn3s, bn3b, bits3, nullptr, nullptr);
    // 5: bconv4 (256->256) + pool + bn4   (profiled slot)
    bconv_px<16, 16, 8, 8, 0, 256, true, 0><<<dim3(256, 8), 128>>>(
        bits3, wb4, K4, bn4s, bn4b, bits4, nullptr, nullptr);
    // 6: bconv5 (256->512) + bn5
    bconv_px<8, 8, 8, 8, 0, 512, false, 0><<<dim3(64, 16), 128>>>(
        bits4, wb5, K5, bn5s, bn5b, bits5, nullptr, nullptr);
    // 7: bconv6 pass A (cin words 0..7) -> partial dots
    bconv_px<8, 8, 16, 8, 0, 512, false, 1><<<dim3(64, 16), 128>>>(
        bits5, wb6, K6A, bn6s, bn6b, nullptr, part, nullptr);
    // 8: bconv6 pass B (cin words 8..15) + partial + relu + pool + bn6 -> h6
    bconv_px<8, 8, 16, 8, 8, 512, true, 2><<<dim3(64, 16), 128>>>(
        bits5, wb6, K6B, bn6s, bn6b, nullptr, part, h6);

    // 9: dense + softmax
    dense_softmax_kernel<<<NB * 4 * 4 * 32 / 256, 256>>>(h6, dw, db, out);
}

// round 11
// speedup vs baseline: 1.9163x; 1.0397x over previous
#include <cuda_runtime.h>
#include <cuda_bf16.h>
#include <cstdint>
#include <math.h>

// ---------------------------------------------------------------------------
// Binarized CNN (XNOR-net) forward pass. Bit-packed XNOR-popcount convs.
// R9: integer-threshold epilogue. For MODE0 layers the whole
//     relu+pool+bn+sign chain collapses to: bit = (2s - V[pat][c] < 0),
//     V = K + C - T with T the exact integer fmaf threshold (always-on
//     sentinel when bias>0). Descending-cout bit packing (shift+or).
//     256-thread blocks. CSA popcount compression as in R8.
// ---------------------------------------------------------------------------

#define NB 128

// Scratch (device globals; no allocation allowed)
__device__ uint32_t g_bits1[NB * 32 * 32 * 4];
__device__ uint32_t g_bits2[NB * 16 * 16 * 4];
__device__ uint32_t g_bits3[NB * 16 * 16 * 8];
__device__ uint32_t g_bits4[NB * 8 * 8 * 8];
__device__ uint32_t g_bits5[NB * 8 * 8 * 16];
__device__ float    g_h6[NB * 4 * 4 * 512];
__device__ int      g_part[NB * 8 * 8 * 512];       // bconv6 partial dots
__device__ uint32_t g_wb2[9 * 4 * 128];
__device__ uint32_t g_wb3[9 * 4 * 256];
__device__ uint32_t g_wb4[9 * 8 * 256];
__device__ uint32_t g_wb5[9 * 8 * 512];
__device__ uint32_t g_wb6[9 * 16 * 512];
// Per-layer tables: layers 2-5 hold V (threshold-folded), layer 6 holds K.
__device__ int g_V2[9 * 128];
__device__ int g_V3[9 * 256];
__device__ int g_V4[9 * 256];
__device__ int g_V5[9 * 512];
__device__ int g_K6A[9 * 512];
__device__ int g_K6B[9 * 512];

// ---------------------------------------------------------------------------
// Weight-sign packing. Layout per layer: [tap(9)][cin_word][cout].
// ---------------------------------------------------------------------------
__device__ __forceinline__ void pack_one(const float* __restrict__ w,
                                         uint32_t* __restrict__ wb,
                                         int idx, int CIN, int COUT) {
    int cout = idx % COUT;
    int tw = idx / COUT;
    int cw = CIN >> 5;
    int wword = tw % cw;
    int tap = tw / cw;
    uint32_t m = 0;
#pragma unroll 8
    for (int j = 0; j < 32; j++) {
        float f = w[(tap * CIN + wword * 32 + j) * COUT + cout];
        m |= (f > 0.0f ? 1u : 0u) << j;
    }
    wb[idx] = m;
}

__global__ void pack_all_kernel(const float* __restrict__ w2, const float* __restrict__ w3,
                                const float* __restrict__ w4, const float* __restrict__ w5,
                                const float* __restrict__ w6,
                                uint32_t* __restrict__ wb2, uint32_t* __restrict__ wb3,
                                uint32_t* __restrict__ wb4, uint32_t* __restrict__ wb5,
                                uint32_t* __restrict__ wb6) {
    int idx = blockIdx.x * blockDim.x + threadIdx.x;
    const int n2 = 9 * 4 * 128, n3 = 9 * 4 * 256, n4 = 9 * 8 * 256,
              n5 = 9 * 8 * 512, n6 = 9 * 16 * 512;
    if (idx < n2) { pack_one(w2, wb2, idx, 128, 128); return; }
    idx -= n2;
    if (idx < n3) { pack_one(w3, wb3, idx, 128, 256); return; }
    idx -= n3;
    if (idx < n4) { pack_one(w4, wb4, idx, 256, 256); return; }
    idx -= n4;
    if (idx < n5) { pack_one(w5, wb5, idx, 256, 512); return; }
    idx -= n5;
    if (idx < n6) { pack_one(w6, wb6, idx, 512, 512); return; }
}

// ---------------------------------------------------------------------------
// K = (valid - 9)*CW*32 + 2 * sum_{invalid taps} popc(w_chunk)
// so that dot_true = C - 2*S_zeropadded + K, C = 9*CW*32.
// ---------------------------------------------------------------------------
__device__ __forceinline__ int k_compute(const uint32_t* __restrict__ wb,
                                         int c, int p, int CINW, int CW, int w0, int COUT) {
    int ty = p / 3, tx = p % 3;
    int sinv = 0, valid = 0;
    for (int ky = 0; ky < 3; ky++) {
        for (int kx = 0; kx < 3; kx++) {
            bool inv = (ty == 0 && ky == 0) || (ty == 2 && ky == 2) ||
                       (tx == 0 && kx == 0) || (tx == 2 && kx == 2);
            if (!inv) { valid++; continue; }
            for (int w = 0; w < CW; w++)
                sinv += __popc(wb[((size_t)(ky * 3 + kx) * CINW + w0 + w) * COUT + c]);
        }
    }
    return (valid - 9) * CW * 32 + 2 * sinv;
}

// V = K + C - T; T = max{ m : fmaf(m,sc,bi) <= 0 }  (exact, same fmaf as
// the runtime predicate). bias>0 => relu makes the bit always 1 => sentinel.
__device__ __forceinline__ void v_one(const uint32_t* __restrict__ wb, int* __restrict__ V,
                                      int idx, int CW, int COUT,
                                      const float* __restrict__ scale,
                                      const float* __restrict__ bias) {
    int c = idx % COUT;
    int p = idx / COUT;
    int K = k_compute(wb, c, p, CW, CW, 0, COUT);
    const int C = 9 * CW * 32;
    float sc = scale[c], bi = bias[c];
    int v;
    if (bi > 0.0f) {
        v = 2 * C + 1;                       // 2s - v < 0 always -> bit 1
    } else {
        float t0 = -bi / sc;
        int T = (int)floorf(t0);
        while (fmaf((float)(T + 1), sc, bi) <= 0.0f) T++;
        while (fmaf((float)T, sc, bi) > 0.0f) T--;
        v = K + C - T;
    }
    V[idx] = v;
}

__device__ __forceinline__ void k_one(const uint32_t* __restrict__ wb, int* __restrict__ K,
                                      int idx, int CINW, int CW, int w0, int COUT) {
    int c = idx % COUT;
    int p = idx / COUT;
    K[idx] = k_compute(wb, c, p, CINW, CW, w0, COUT);
}

__global__ void tab_all_kernel(const uint32_t* __restrict__ wb2, const uint32_t* __restrict__ wb3,
                               const uint32_t* __restrict__ wb4, const uint32_t* __restrict__ wb5,
                               const uint32_t* __restrict__ wb6,
                               const float* s2, const float* b2, const float* s3, const float* b3,
                               const float* s4, const float* b4, const float* s5, const float* b5,
                               int* V2, int* V3, int* V4, int* V5, int* K6A, int* K6B) {
    int idx = blockIdx.x * blockDim.x + threadIdx.x;
    const int t2 = 9 * 128, t3 = 9 * 256, t4 = 9 * 256, t5 = 9 * 512, t6 = 9 * 512;
    if (idx < t2) { v_one(wb2, V2, idx, 4, 128, s2, b2); return; }
    idx -= t2;
    if (idx < t3) { v_one(wb3, V3, idx, 4, 256, s3, b3); return; }
    idx -= t3;
    if (idx < t4) { v_one(wb4, V4, idx, 8, 256, s4, b4); return; }
    idx -= t4;
    if (idx < t5) { v_one(wb5, V5, idx, 8, 512, s5, b5); return; }
    idx -= t5;
    if (idx < t6) { k_one(wb6, K6A, idx, 16, 8, 0, 512); return; }
    idx -= t6;
    if (idx < t6) { k_one(wb6, K6B, idx, 16, 8, 8, 512); return; }
}

// ---------------------------------------------------------------------------
// conv1: float 3x3 SAME conv (3->128) + bias + relu + bn + binarize + pack
// ---------------------------------------------------------------------------
__global__ void conv1_kernel(const float* __restrict__ x, const float* __restrict__ w1,
                             const float* __restrict__ b1, const float* __restrict__ s1,
                             const float* __restrict__ bb1, uint32_t* __restrict__ obits) {
    int p = blockIdx.x;
    int co = threadIdx.x;
    int xx = p & 31;
    int y = (p >> 5) & 31;
    int n = p >> 10;
    float acc = 0.0f;
#pragma unroll
    for (int ky = 0; ky < 3; ky++) {
        int iy = y + ky - 1;
        if ((unsigned)iy >= 32u) continue;
#pragma unroll
        for (int kx = 0; kx < 3; kx++) {
            int ix = xx + kx - 1;
            if ((unsigned)ix >= 32u) continue;
            const float* xp = x + ((n * 32 + iy) * 32 + ix) * 3;
            const float* wp = w1 + ((ky * 3 + kx) * 3) * 128 + co;
            acc = fmaf(xp[0], wp[0], acc);
            acc = fmaf(xp[1], wp[128], acc);
            acc = fmaf(xp[2], wp[256], acc);
        }
    }
    float v = fmaxf(acc + b1[co], 0.0f);
    v = fmaf(v, s1[co], bb1[co]);
    unsigned mask = __ballot_sync(0xffffffffu, v > 0.0f);
    if ((co & 31) == 0) obits[p * 4 + (co >> 5)] = mask;
}

// Full adder (carry-save): s = xor3 (LOP3 0x96), c = majority (LOP3 0xE8).
__device__ __forceinline__ void csa(uint32_t a, uint32_t b, uint32_t d,
                                    uint32_t& s, uint32_t& c) {
    s = a ^ b ^ d;
    c = (a & b) | (d & (a ^ b));
}

// ---------------------------------------------------------------------------
// Binary conv, lane = pixel, CSA-compressed popcount.
//   MODE: 0 = V-threshold -> bits out; 1 = store partial int dots (tab = K);
//         2 = final float out adding partials (tab = K).
// Warp strip: RS rows x CS cols (CS = min(W,16), RS = 32/CS).
// Grid: x = (NB*H*W/32)/8 blocks of 8 warps, y = COUT/32.
// ---------------------------------------------------------------------------
template <int H, int W, int CINW, int CW, int W0, int COUT, bool POOL, int MODE>
__global__ void __launch_bounds__(256) bconv_px(
    const uint32_t* __restrict__ abits, const uint32_t* __restrict__ wbits,
    const int* __restrict__ tab, const float* __restrict__ scale,
    const float* __restrict__ bias, uint32_t* __restrict__ obits,
    int* __restrict__ part, float* __restrict__ ofloat) {
    constexpr int NT = 256;
    constexpr int CS = (W < 16) ? W : 16;
    constexpr int RS = 32 / CS;
    constexpr int SPI = (H * W) / 32;       // strips per image
    constexpr int WCS = W / CS;             // col-strips per row-group
    constexpr int TPW = 9 * CW / 4;         // uint4 per cout
    constexpr int NBLK = (9 * CW) / 36;     // 36-word CSA blocks
    constexpr int NPIX = NB * H * W;
    constexpr int C0 = 9 * CW * 32;

    __shared__ uint4 sw4[32 * TPW];
    __shared__ int sk[9 * 33];
    __shared__ float ssc[32], sbi[32];

    const int g = blockIdx.y;
    {
        uint32_t* sws = (uint32_t*)sw4;
        for (int idx = threadIdx.x; idx < 32 * 9 * CW; idx += NT) {
            int c = idx / (9 * CW);
            int t = idx - c * (9 * CW);
            int tap = t / CW, w = t - tap * CW;
            sws[idx] = wbits[((size_t)tap * CINW + W0 + w) * COUT + g * 32 + c];
        }
        for (int idx = threadIdx.x; idx < 9 * 32; idx += NT) {
            int p = idx >> 5, c = idx & 31;
            sk[p * 33 + c] = tab[p * COUT + g * 32 + c];
        }
        if (threadIdx.x < 32) {
            ssc[threadIdx.x] = scale[g * 32 + threadIdx.x];
            sbi[threadIdx.x] = bias[g * 32 + threadIdx.x];
        }
    }
    __syncthreads();

    const int lane = threadIdx.x & 31;
    const int warp = threadIdx.x >> 5;
    const int sid = blockIdx.x * 8 + warp;
    const int n = sid / SPI;
    const int si = sid - n * SPI;
    const int rowg = si / WCS;
    const int colg = si - rowg * WCS;
    const int r = lane / CS;
    const int x = lane - r * CS;
    const int py = rowg * RS + r;
    const int px = colg * CS + x;

    // Activation patch (zero-filled outside the image)
    uint4 patch[TPW];
#pragma unroll
    for (int ky = 0; ky < 3; ky++) {
#pragma unroll
        for (int kx = 0; kx < 3; kx++) {
            int iy = py + ky - 1, ix = px + kx - 1;
            bool ok = ((unsigned)iy < (unsigned)H) && ((unsigned)ix < (unsigned)W);
            const uint4* ap =
                (const uint4*)(abits + ((size_t)(n * H + iy) * W + ix) * CINW + W0);
#pragma unroll
            for (int q = 0; q < CW / 4; q++) {
                uint4 a = make_uint4(0u, 0u, 0u, 0u);
                if (ok) a = __ldg(ap + q);
                patch[(ky * 3 + kx) * (CW / 4) + q] = a;
            }
        }
    }

    const int ty = (py == 0) ? 0 : ((py == H - 1) ? 2 : 1);
    const int txp = (px == 0) ? 0 : ((px == W - 1) ? 2 : 1);
    const int pat = ty * 3 + txp;
    const int gpix = (n * H + py) * W + px;

    uint32_t word = 0;
#pragma unroll 1
    for (int c = 31; c >= 0; c--) {
        const uint4* wr = &sw4[c * TPW];
        const int dv = sk[pat * 33 + c];    // V (MODE 0) or K (MODE 1/2)
        int s = 0;
#pragma unroll
        for (int blk = 0; blk < NBLK; blk++) {
            // XOR 36 words
            uint32_t xw[36];
#pragma unroll
            for (int t = 0; t < 9; t++) {
                uint4 wv = wr[blk * 9 + t];      // warp-uniform -> LDS broadcast
                uint4 av = patch[blk * 9 + t];
                xw[t * 4 + 0] = av.x ^ wv.x;
                xw[t * 4 + 1] = av.y ^ wv.y;
                xw[t * 4 + 2] = av.z ^ wv.z;
                xw[t * 4 + 3] = av.w ^ wv.w;
            }
            // CSA level 1: 36 -> 12 s1 (wt1) + 12 c1 (wt2)
            uint32_t s1[12], c1[12];
#pragma unroll
            for (int i = 0; i < 12; i++)
                csa(xw[3 * i], xw[3 * i + 1], xw[3 * i + 2], s1[i], c1[i]);
            // CSA level 2
            uint32_t s2[4], c2[4], t2[4], d4[4];
#pragma unroll
            for (int i = 0; i < 4; i++)
                csa(s1[3 * i], s1[3 * i + 1], s1[3 * i + 2], s2[i], c2[i]);
#pragma unroll
            for (int i = 0; i < 4; i++)
                csa(c1[3 * i], c1[3 * i + 1], c1[3 * i + 2], t2[i], d4[i]);
            int A = __popc(s2[0]) + __popc(s2[1]) + __popc(s2[2]) + __popc(s2[3]);
            int B = __popc(c2[0]) + __popc(c2[1]) + __popc(c2[2]) + __popc(c2[3]) +
                    __popc(t2[0]) + __popc(t2[1]) + __popc(t2[2]) + __popc(t2[3]);
            int C = __popc(d4[0]) + __popc(d4[1]) + __popc(d4[2]) + __popc(d4[3]);
            s += A + 2 * (B + 2 * C);       // exact popcount sum of the 36 words
        }

        if constexpr (MODE == 0) {
            int z = 2 * s - dv;             // bit = (max-dot > T) via sign
            if constexpr (POOL) {
                z = min(z, __shfl_xor_sync(0xffffffffu, z, 1));
                z = min(z, __shfl_xor_sync(0xffffffffu, z, CS));
            }
            word = (word << 1) | ((uint32_t)z >> 31);
        } else if constexpr (MODE == 1) {
            part[(size_t)(g * 32 + c) * NPIX + gpix] = C0 - 2 * s + dv;
        } else {
            int m = C0 - 2 * s + dv + __ldg(part + (size_t)(g * 32 + c) * NPIX + gpix);
            m = max(m, 0);                  // relu (before pool is exact)
            if constexpr (POOL) {
                m = max(m, __shfl_xor_sync(0xffffffffu, m, 1));
                m = max(m, __shfl_xor_sync(0xffffffffu, m, CS));
            }
            float v = fmaf((float)m, ssc[c], sbi[c]);
            if (((r & 1) == 0) && ((x & 1) == 0)) {
                int opix = (n * (H / 2) + (py >> 1)) * (W / 2) + (px >> 1);
                ofloat[(size_t)opix * COUT + g * 32 + c] = v;
            }
        }
    }

    if constexpr (MODE == 0) {
        if constexpr (POOL) {
            if (((r & 1) == 0) && ((x & 1) == 0)) {
                int opix = (n * (H / 2) + (py >> 1)) * (W / 2) + (px >> 1);
                obits[(size_t)opix * (COUT / 32) + g] = word;
            }
        } else {
            obits[(size_t)gpix * (COUT / 32) + g] = word;
        }
    }
}

// ---------------------------------------------------------------------------
// Dense (512->10) + softmax, one warp per output pixel.
// ---------------------------------------------------------------------------
__global__ void dense_softmax_kernel(const float* __restrict__ h, const float* __restrict__ dw,
                                     const float* __restrict__ db, float* __restrict__ out) {
    int warp = (blockIdx.x * blockDim.x + threadIdx.x) >> 5;
    int lane = threadIdx.x & 31;
    if (warp >= NB * 4 * 4) return;
    float acc[10];
#pragma unroll
    for (int j = 0; j < 10; j++) acc[j] = 0.0f;
    const float* hp = h + (size_t)warp * 512;
#pragma unroll
    for (int k = 0; k < 16; k++) {
        int cc = k * 32 + lane;
        float hv = hp[cc];
        const float* wp = dw + cc * 10;
#pragma unroll
        for (int j = 0; j < 10; j++) acc[j] = fmaf(hv, __ldg(wp + j), acc[j]);
    }
#pragma unroll
    for (int s = 16; s > 0; s >>= 1) {
#pragma unroll
        for (int j = 0; j < 10; j++) acc[j] += __shfl_xor_sync(0xffffffffu, acc[j], s);
    }
    if (lane == 0) {
        float l[10], m = -1e30f;
#pragma unroll
        for (int j = 0; j < 10; j++) { l[j] = acc[j] + db[j]; m = fmaxf(m, l[j]); }
        float sum = 0.0f;
#pragma unroll
        for (int j = 0; j < 10; j++) { l[j] = expf(l[j] - m); sum += l[j]; }
        float inv = 1.0f / sum;
#pragma unroll
        for (int j = 0; j < 10; j++) out[warp * 10 + j] = l[j] * inv;
    }
}

// ---------------------------------------------------------------------------
// Launch. Input order: 0:x 1:w1 2:b1 3:w2 4:w3 5:w4 6:w5 7:w6
//  8..19: bn{1..6}_scale/bias interleaved, 20:dense_w 21:dense_b
// ---------------------------------------------------------------------------
extern "C" void kernel_launch(void* const* d_in, const int* in_sizes, int n_in,
                              void* d_out, int out_size) {
    const float* x   = (const float*)d_in[0];
    const float* w1  = (const float*)d_in[1];
    const float* b1  = (const float*)d_in[2];
    const float* w2  = (const float*)d_in[3];
    const float* w3  = (const float*)d_in[4];
    const float* w4  = (const float*)d_in[5];
    const float* w5  = (const float*)d_in[6];
    const float* w6  = (const float*)d_in[7];
    const float* bn1s = (const float*)d_in[8];
    const float* bn1b = (const float*)d_in[9];
    const float* bn2s = (const float*)d_in[10];
    const float* bn2b = (const float*)d_in[11];
    const float* bn3s = (const float*)d_in[12];
    const float* bn3b = (const float*)d_in[13];
    const float* bn4s = (const float*)d_in[14];
    const float* bn4b = (const float*)d_in[15];
    const float* bn5s = (const float*)d_in[16];
    const float* bn5b = (const float*)d_in[17];
    const float* bn6s = (const float*)d_in[18];
    const float* bn6b = (const float*)d_in[19];
    const float* dw   = (const float*)d_in[20];
    const float* db   = (const float*)d_in[21];
    float* out = (float*)d_out;

    uint32_t *bits1, *bits2, *bits3, *bits4, *bits5;
    uint32_t *wb2, *wb3, *wb4, *wb5, *wb6;
    int *V2, *V3, *V4, *V5, *K6A, *K6B, *part;
    float* h6;
    cudaGetSymbolAddress((void**)&bits1, g_bits1);
    cudaGetSymbolAddress((void**)&bits2, g_bits2);
    cudaGetSymbolAddress((void**)&bits3, g_bits3);
    cudaGetSymbolAddress((void**)&bits4, g_bits4);
    cudaGetSymbolAddress((void**)&bits5, g_bits5);
    cudaGetSymbolAddress((void**)&wb2, g_wb2);
    cudaGetSymbolAddress((void**)&wb3, g_wb3);
    cudaGetSymbolAddress((void**)&wb4, g_wb4);
    cudaGetSymbolAddress((void**)&wb5, g_wb5);
    cudaGetSymbolAddress((void**)&wb6, g_wb6);
    cudaGetSymbolAddress((void**)&V2, g_V2);
    cudaGetSymbolAddress((void**)&V3, g_V3);
    cudaGetSymbolAddress((void**)&V4, g_V4);
    cudaGetSymbolAddress((void**)&V5, g_V5);
    cudaGetSymbolAddress((void**)&K6A, g_K6A);
    cudaGetSymbolAddress((void**)&K6B, g_K6B);
    cudaGetSymbolAddress((void**)&part, g_part);
    cudaGetSymbolAddress((void**)&h6, g_h6);

    // 0: weight packing
    const int npack = 9 * 4 * 128 + 9 * 4 * 256 + 9 * 8 * 256 + 9 * 8 * 512 + 9 * 16 * 512;
    pack_all_kernel<<<(npack + 255) / 256, 256>>>(w2, w3, w4, w5, w6,
                                                  wb2, wb3, wb4, wb5, wb6);
    // 1: V/K tables
    const int nk = 9 * (128 + 256 + 256 + 512 + 512 + 512);
    tab_all_kernel<<<(nk + 255) / 256, 256>>>(wb2, wb3, wb4, wb5, wb6,
                                              bn2s, bn2b, bn3s, bn3b,
                                              bn4s, bn4b, bn5s, bn5b,
                                              V2, V3, V4, V5, K6A, K6B);

    // 2: conv1 + relu + bn1 + binarize
    conv1_kernel<<<NB * 32 * 32, 128>>>(x, w1, b1, bn1s, bn1b, bits1);

    // 3: bconv2 (128->128) + pool + bn2   strips 4096 / 8 warps
    bconv_px<32, 32, 4, 4, 0, 128, true, 0><<<dim3(512, 4), 256>>>(
        bits1, wb2, V2, bn2s, bn2b, bits2, nullptr, nullptr);
    // 4: bconv3 (128->256) + bn3          strips 1024
    bconv_px<16, 16, 4, 4, 0, 256, false, 0><<<dim3(128, 8), 256>>>(
        bits2, wb3, V3, bn3s, bn3b, bits3, nullptr, nullptr);
    // 5: bconv4 (256->256) + pool + bn4   (profiled slot)
    bconv_px<16, 16, 8, 8, 0, 256, true, 0><<<dim3(128, 8), 256>>>(
        bits3, wb4, V4, bn4s, bn4b, bits4, nullptr, nullptr);
    // 6: bconv5 (256->512) + bn5          strips 256
    bconv_px<8, 8, 8, 8, 0, 512, false, 0><<<dim3(32, 16), 256>>>(
        bits4, wb5, V5, bn5s, bn5b, bits5, nullptr, nullptr);
    // 7: bconv6 pass A (cin words 0..7) -> partial dots
    bconv_px<8, 8, 16, 8, 0, 512, false, 1><<<dim3(32, 16), 256>>>(
        bits5, wb6, K6A, bn6s, bn6b, nullptr, part, nullptr);
    // 8: bconv6 pass B (cin words 8..15) + partial + relu + pool + bn6 -> h6
    bconv_px<8, 8, 16, 8, 8, 512, true, 2><<<dim3(32, 16), 256>>>(
        bits5, wb6, K6B, bn6s, bn6b, nullptr, part, h6);

    // 9: dense + softmax
    dense_softmax_kernel<<<NB * 4 * 4 * 32 / 256, 256>>>(h6, dw, db, out);
}

// round 12
// speedup vs baseline: 1.9331x; 1.0088x over previous
#include <cuda_runtime.h>
#include <cuda_bf16.h>
#include <cstdint>
#include <math.h>

// ---------------------------------------------------------------------------
// Binarized CNN (XNOR-net) forward pass. Bit-packed XNOR-popcount convs.
// R12: full Wallace/CSA reduction (16 -> 7 popcount words per 36-word block,
//      POPC is quarter-rate vs full-rate LOP3) + conv1 restructured to 8
//      pixels/block with register-resident weights. Integer-threshold
//      epilogue (V tables), lane=pixel mapping, broadcast SMEM weights,
//      shfl maxpool, bconv6 as two cin-half passes. All exact integer math.
// ---------------------------------------------------------------------------

#define NB 128

// Scratch (device globals; no allocation allowed)
__device__ uint32_t g_bits1[NB * 32 * 32 * 4];
__device__ uint32_t g_bits2[NB * 16 * 16 * 4];
__device__ uint32_t g_bits3[NB * 16 * 16 * 8];
__device__ uint32_t g_bits4[NB * 8 * 8 * 8];
__device__ uint32_t g_bits5[NB * 8 * 8 * 16];
__device__ float    g_h6[NB * 4 * 4 * 512];
__device__ int      g_part[NB * 8 * 8 * 512];       // bconv6 partial dots
__device__ uint32_t g_wb2[9 * 4 * 128];
__device__ uint32_t g_wb3[9 * 4 * 256];
__device__ uint32_t g_wb4[9 * 8 * 256];
__device__ uint32_t g_wb5[9 * 8 * 512];
__device__ uint32_t g_wb6[9 * 16 * 512];
// Per-layer tables: layers 2-5 hold V (threshold-folded), layer 6 holds K.
__device__ int g_V2[9 * 128];
__device__ int g_V3[9 * 256];
__device__ int g_V4[9 * 256];
__device__ int g_V5[9 * 512];
__device__ int g_K6A[9 * 512];
__device__ int g_K6B[9 * 512];

// ---------------------------------------------------------------------------
// Weight-sign packing. Layout per layer: [tap(9)][cin_word][cout].
// ---------------------------------------------------------------------------
__device__ __forceinline__ void pack_one(const float* __restrict__ w,
                                         uint32_t* __restrict__ wb,
                                         int idx, int CIN, int COUT) {
    int cout = idx % COUT;
    int tw = idx / COUT;
    int cw = CIN >> 5;
    int wword = tw % cw;
    int tap = tw / cw;
    uint32_t m = 0;
#pragma unroll 8
    for (int j = 0; j < 32; j++) {
        float f = w[(tap * CIN + wword * 32 + j) * COUT + cout];
        m |= (f > 0.0f ? 1u : 0u) << j;
    }
    wb[idx] = m;
}

__global__ void pack_all_kernel(const float* __restrict__ w2, const float* __restrict__ w3,
                                const float* __restrict__ w4, const float* __restrict__ w5,
                                const float* __restrict__ w6,
                                uint32_t* __restrict__ wb2, uint32_t* __restrict__ wb3,
                                uint32_t* __restrict__ wb4, uint32_t* __restrict__ wb5,
                                uint32_t* __restrict__ wb6) {
    int idx = blockIdx.x * blockDim.x + threadIdx.x;
    const int n2 = 9 * 4 * 128, n3 = 9 * 4 * 256, n4 = 9 * 8 * 256,
              n5 = 9 * 8 * 512, n6 = 9 * 16 * 512;
    if (idx < n2) { pack_one(w2, wb2, idx, 128, 128); return; }
    idx -= n2;
    if (idx < n3) { pack_one(w3, wb3, idx, 128, 256); return; }
    idx -= n3;
    if (idx < n4) { pack_one(w4, wb4, idx, 256, 256); return; }
    idx -= n4;
    if (idx < n5) { pack_one(w5, wb5, idx, 256, 512); return; }
    idx -= n5;
    if (idx < n6) { pack_one(w6, wb6, idx, 512, 512); return; }
}

// ---------------------------------------------------------------------------
// K = (valid - 9)*CW*32 + 2 * sum_{invalid taps} popc(w_chunk)
// so that dot_true = C - 2*S_zeropadded + K, C = 9*CW*32.
// ---------------------------------------------------------------------------
__device__ __forceinline__ int k_compute(const uint32_t* __restrict__ wb,
                                         int c, int p, int CINW, int CW, int w0, int COUT) {
    int ty = p / 3, tx = p % 3;
    int sinv = 0, valid = 0;
    for (int ky = 0; ky < 3; ky++) {
        for (int kx = 0; kx < 3; kx++) {
            bool inv = (ty == 0 && ky == 0) || (ty == 2 && ky == 2) ||
                       (tx == 0 && kx == 0) || (tx == 2 && kx == 2);
            if (!inv) { valid++; continue; }
            for (int w = 0; w < CW; w++)
                sinv += __popc(wb[((size_t)(ky * 3 + kx) * CINW + w0 + w) * COUT + c]);
        }
    }
    return (valid - 9) * CW * 32 + 2 * sinv;
}

// V = K + C - T; T = max{ m : fmaf(m,sc,bi) <= 0 }  (exact, same fmaf as
// the runtime predicate). bias>0 => relu makes the bit always 1 => sentinel.
__device__ __forceinline__ void v_one(const uint32_t* __restrict__ wb, int* __restrict__ V,
                                      int idx, int CW, int COUT,
                                      const float* __restrict__ scale,
                                      const float* __restrict__ bias) {
    int c = idx % COUT;
    int p = idx / COUT;
    int K = k_compute(wb, c, p, CW, CW, 0, COUT);
    const int C = 9 * CW * 32;
    float sc = scale[c], bi = bias[c];
    int v;
    if (bi > 0.0f) {
        v = 2 * C + 1;                       // 2s - v < 0 always -> bit 1
    } else {
        float t0 = -bi / sc;
        int T = (int)floorf(t0);
        while (fmaf((float)(T + 1), sc, bi) <= 0.0f) T++;
        while (fmaf((float)T, sc, bi) > 0.0f) T--;
        v = K + C - T;
    }
    V[idx] = v;
}

__device__ __forceinline__ void k_one(const uint32_t* __restrict__ wb, int* __restrict__ K,
                                      int idx, int CINW, int CW, int w0, int COUT) {
    int c = idx % COUT;
    int p = idx / COUT;
    K[idx] = k_compute(wb, c, p, CINW, CW, w0, COUT);
}

__global__ void tab_all_kernel(const uint32_t* __restrict__ wb2, const uint32_t* __restrict__ wb3,
                               const uint32_t* __restrict__ wb4, const uint32_t* __restrict__ wb5,
                               const uint32_t* __restrict__ wb6,
                               const float* s2, const float* b2, const float* s3, const float* b3,
                               const float* s4, const float* b4, const float* s5, const float* b5,
                               int* V2, int* V3, int* V4, int* V5, int* K6A, int* K6B) {
    int idx = blockIdx.x * blockDim.x + threadIdx.x;
    const int t2 = 9 * 128, t3 = 9 * 256, t4 = 9 * 256, t5 = 9 * 512, t6 = 9 * 512;
    if (idx < t2) { v_one(wb2, V2, idx, 4, 128, s2, b2); return; }
    idx -= t2;
    if (idx < t3) { v_one(wb3, V3, idx, 4, 256, s3, b3); return; }
    idx -= t3;
    if (idx < t4) { v_one(wb4, V4, idx, 8, 256, s4, b4); return; }
    idx -= t4;
    if (idx < t5) { v_one(wb5, V5, idx, 8, 512, s5, b5); return; }
    idx -= t5;
    if (idx < t6) { k_one(wb6, K6A, idx, 16, 8, 0, 512); return; }
    idx -= t6;
    if (idx < t6) { k_one(wb6, K6B, idx, 16, 8, 8, 512); return; }
}

// ---------------------------------------------------------------------------
// conv1: float 3x3 SAME conv (3->128) + bias + relu + bn + binarize + pack.
// 8 consecutive pixels per block; 27 weights register-resident.
// ---------------------------------------------------------------------------
__global__ void __launch_bounds__(128) conv1_kernel(
    const float* __restrict__ x, const float* __restrict__ w1,
    const float* __restrict__ b1, const float* __restrict__ s1,
    const float* __restrict__ bb1, uint32_t* __restrict__ obits) {
    constexpr int PIX = 8;
    const int co = threadIdx.x;

    float wreg[27];
#pragma unroll
    for (int t = 0; t < 27; t++) wreg[t] = __ldg(w1 + t * 128 + co);
    const float bb = __ldg(b1 + co);
    const float sc = __ldg(s1 + co);
    const float bi = __ldg(bb1 + co);

    const int p0 = blockIdx.x * PIX;        // 8 consecutive x in one row
    const int y = (p0 >> 5) & 31;
    const int n = p0 >> 10;
    const int x0 = p0 & 31;

#pragma unroll 1
    for (int pp = 0; pp < PIX; pp++) {
        int xx = x0 + pp;
        float acc = 0.0f;
#pragma unroll
        for (int ky = 0; ky < 3; ky++) {
            int iy = y + ky - 1;
            if ((unsigned)iy >= 32u) continue;
#pragma unroll
            for (int kx = 0; kx < 3; kx++) {
                int ix = xx + kx - 1;
                if ((unsigned)ix >= 32u) continue;
                const float* xp = x + ((n * 32 + iy) * 32 + ix) * 3;
                const float* wr = wreg + (ky * 3 + kx) * 3;
                acc = fmaf(xp[0], wr[0], acc);
                acc = fmaf(xp[1], wr[1], acc);
                acc = fmaf(xp[2], wr[2], acc);
            }
        }
        float v = fmaxf(acc + bb, 0.0f);
        v = fmaf(v, sc, bi);
        unsigned mask = __ballot_sync(0xffffffffu, v > 0.0f);
        if ((co & 31) == 0) obits[(p0 + pp) * 4 + (co >> 5)] = mask;
    }
}

// Full adder (carry-save): s = xor3 (LOP3 0x96), c = majority (LOP3 0xE8).
__device__ __forceinline__ void csa(uint32_t a, uint32_t b, uint32_t d,
                                    uint32_t& s, uint32_t& c) {
    s = a ^ b ^ d;
    c = (a & b) | (d & (a ^ b));
}

// ---------------------------------------------------------------------------
// Binary conv, lane = pixel, full Wallace-tree popcount (7 POPCs / 36 words).
//   MODE: 0 = V-threshold -> bits out; 1 = store partial int dots (tab = K);
//         2 = final float out adding partials (tab = K).
// Warp strip: RS rows x CS cols (CS = min(W,16), RS = 32/CS).
// Grid: x = (NB*H*W/32)/8 blocks of 8 warps, y = COUT/32.
// ---------------------------------------------------------------------------
template <int H, int W, int CINW, int CW, int W0, int COUT, bool POOL, int MODE>
__global__ void __launch_bounds__(256) bconv_px(
    const uint32_t* __restrict__ abits, const uint32_t* __restrict__ wbits,
    const int* __restrict__ tab, const float* __restrict__ scale,
    const float* __restrict__ bias, uint32_t* __restrict__ obits,
    int* __restrict__ part, float* __restrict__ ofloat) {
    constexpr int NT = 256;
    constexpr int CS = (W < 16) ? W : 16;
    constexpr int RS = 32 / CS;
    constexpr int SPI = (H * W) / 32;       // strips per image
    constexpr int WCS = W / CS;             // col-strips per row-group
    constexpr int TPW = 9 * CW / 4;         // uint4 per cout
    constexpr int NBLK = (9 * CW) / 36;     // 36-word CSA blocks
    constexpr int NPIX = NB * H * W;
    constexpr int C0 = 9 * CW * 32;

    __shared__ uint4 sw4[32 * TPW];
    __shared__ int sk[9 * 33];
    __shared__ float ssc[32], sbi[32];

    const int g = blockIdx.y;
    {
        uint32_t* sws = (uint32_t*)sw4;
        for (int idx = threadIdx.x; idx < 32 * 9 * CW; idx += NT) {
            int c = idx / (9 * CW);
            int t = idx - c * (9 * CW);
            int tap = t / CW, w = t - tap * CW;
            sws[idx] = wbits[((size_t)tap * CINW + W0 + w) * COUT + g * 32 + c];
        }
        for (int idx = threadIdx.x; idx < 9 * 32; idx += NT) {
            int p = idx >> 5, c = idx & 31;
            sk[p * 33 + c] = tab[p * COUT + g * 32 + c];
        }
        if (threadIdx.x < 32) {
            ssc[threadIdx.x] = scale[g * 32 + threadIdx.x];
            sbi[threadIdx.x] = bias[g * 32 + threadIdx.x];
        }
    }
    __syncthreads();

    const int lane = threadIdx.x & 31;
    const int warp = threadIdx.x >> 5;
    const int sid = blockIdx.x * 8 + warp;
    const int n = sid / SPI;
    const int si = sid - n * SPI;
    const int rowg = si / WCS;
    const int colg = si - rowg * WCS;
    const int r = lane / CS;
    const int x = lane - r * CS;
    const int py = rowg * RS + r;
    const int px = colg * CS + x;

    // Activation patch (zero-filled outside the image)
    uint4 patch[TPW];
#pragma unroll
    for (int ky = 0; ky < 3; ky++) {
#pragma unroll
        for (int kx = 0; kx < 3; kx++) {
            int iy = py + ky - 1, ix = px + kx - 1;
            bool ok = ((unsigned)iy < (unsigned)H) && ((unsigned)ix < (unsigned)W);
            const uint4* ap =
                (const uint4*)(abits + ((size_t)(n * H + iy) * W + ix) * CINW + W0);
#pragma unroll
            for (int q = 0; q < CW / 4; q++) {
                uint4 a = make_uint4(0u, 0u, 0u, 0u);
                if (ok) a = __ldg(ap + q);
                patch[(ky * 3 + kx) * (CW / 4) + q] = a;
            }
        }
    }

    const int ty = (py == 0) ? 0 : ((py == H - 1) ? 2 : 1);
    const int txp = (px == 0) ? 0 : ((px == W - 1) ? 2 : 1);
    const int pat = ty * 3 + txp;
    const int gpix = (n * H + py) * W + px;

    uint32_t word = 0;
#pragma unroll 1
    for (int c = 31; c >= 0; c--) {
        const uint4* wr = &sw4[c * TPW];
        const int dv = sk[pat * 33 + c];    // V (MODE 0) or K (MODE 1/2)
        int s = 0;
#pragma unroll
        for (int blk = 0; blk < NBLK; blk++) {
            // XOR 36 words
            uint32_t xw[36];
#pragma unroll
            for (int t = 0; t < 9; t++) {
                uint4 wv = wr[blk * 9 + t];      // warp-uniform -> LDS broadcast
                uint4 av = patch[blk * 9 + t];
                xw[t * 4 + 0] = av.x ^ wv.x;
                xw[t * 4 + 1] = av.y ^ wv.y;
                xw[t * 4 + 2] = av.z ^ wv.z;
                xw[t * 4 + 3] = av.w ^ wv.w;
            }
            // L1: 36 -> 12 s1 (wt1) + 12 c1 (wt2)
            uint32_t s1[12], c1[12];
#pragma unroll
            for (int i = 0; i < 12; i++)
                csa(xw[3 * i], xw[3 * i + 1], xw[3 * i + 2], s1[i], c1[i]);
            // L2: 12 wt1 -> 4 s2(wt1) + 4 c2(wt2); 12 wt2 -> 4 t2(wt2) + 4 d4(wt4)
            uint32_t s2[4], c2[4], t2[4], d4[4];
#pragma unroll
            for (int i = 0; i < 4; i++)
                csa(s1[3 * i], s1[3 * i + 1], s1[3 * i + 2], s2[i], c2[i]);
#pragma unroll
            for (int i = 0; i < 4; i++)
                csa(c1[3 * i], c1[3 * i + 1], c1[3 * i + 2], t2[i], d4[i]);
            // L3: full reduction to 7 popcount words.
            uint32_t sa, ca;                         // wt1 -> sa(wt1), ca(wt2)
            csa(s2[0], s2[1], s2[2], sa, ca);
            uint32_t u1, v1, u2, v2, u3, v3, ub, vb; // wt2 pool (9 words)
            csa(c2[0], c2[1], c2[2], u1, v1);
            csa(c2[3], t2[0], t2[1], u2, v2);
            csa(t2[2], t2[3], ca, u3, v3);
            csa(u1, u2, u3, ub, vb);                 // wt2 left: ub
            uint32_t e1, f1, e2, f2, e3, f3;         // wt4 pool (8 words)
            csa(d4[0], d4[1], d4[2], e1, f1);
            csa(d4[3], v1, v2, e2, f2);
            csa(v3, vb, e1, e3, f3);                 // wt4 left: e2, e3
            uint32_t gg, hh;                         // wt8 pool (3 words)
            csa(f1, f2, f3, gg, hh);                 // wt8: gg, wt16: hh
            int P1 = __popc(sa) + __popc(s2[3]);
            int P2 = __popc(ub);
            int P4 = __popc(e2) + __popc(e3);
            int P8 = __popc(gg);
            int P16 = __popc(hh);
            s += P1 + 2 * (P2 + 2 * (P4 + 2 * (P8 + 2 * P16)));
        }

        if constexpr (MODE == 0) {
            int z = 2 * s - dv;             // bit = (max-dot > T) via sign
            if constexpr (POOL) {
                z = min(z, __shfl_xor_sync(0xffffffffu, z, 1));
                z = min(z, __shfl_xor_sync(0xffffffffu, z, CS));
            }
            word = (word << 1) | ((uint32_t)z >> 31);
        } else if constexpr (MODE == 1) {
            part[(size_t)(g * 32 + c) * NPIX + gpix] = C0 - 2 * s + dv;
        } else {
            int m = C0 - 2 * s + dv + __ldg(part + (size_t)(g * 32 + c) * NPIX + gpix);
            m = max(m, 0);                  // relu (before pool is exact)
            if constexpr (POOL) {
                m = max(m, __shfl_xor_sync(0xffffffffu, m, 1));
                m = max(m, __shfl_xor_sync(0xffffffffu, m, CS));
            }
            float v = fmaf((float)m, ssc[c], sbi[c]);
            if (((r & 1) == 0) && ((x & 1) == 0)) {
                int opix = (n * (H / 2) + (py >> 1)) * (W / 2) + (px >> 1);
                ofloat[(size_t)opix * COUT + g * 32 + c] = v;
            }
        }
    }

    if constexpr (MODE == 0) {
        if constexpr (POOL) {
            if (((r & 1) == 0) && ((x & 1) == 0)) {
                int opix = (n * (H / 2) + (py >> 1)) * (W / 2) + (px >> 1);
                obits[(size_t)opix * (COUT / 32) + g] = word;
            }
        } else {
            obits[(size_t)gpix * (COUT / 32) + g] = word;
        }
    }
}

// ---------------------------------------------------------------------------
// Dense (512->10) + softmax, one warp per output pixel.
// ---------------------------------------------------------------------------
__global__ void dense_softmax_kernel(const float* __restrict__ h, const float* __restrict__ dw,
                                     const float* __restrict__ db, float* __restrict__ out) {
    int warp = (blockIdx.x * blockDim.x + threadIdx.x) >> 5;
    int lane = threadIdx.x & 31;
    if (warp >= NB * 4 * 4) return;
    float acc[10];
#pragma unroll
    for (int j = 0; j < 10; j++) acc[j] = 0.0f;
    const float* hp = h + (size_t)warp * 512;
#pragma unroll
    for (int k = 0; k < 16; k++) {
        int cc = k * 32 + lane;
        float hv = hp[cc];
        const float* wp = dw + cc * 10;
#pragma unroll
        for (int j = 0; j < 10; j++) acc[j] = fmaf(hv, __ldg(wp + j), acc[j]);
    }
#pragma unroll
    for (int s = 16; s > 0; s >>= 1) {
#pragma unroll
        for (int j = 0; j < 10; j++) acc[j] += __shfl_xor_sync(0xffffffffu, acc[j], s);
    }
    if (lane == 0) {
        float l[10], m = -1e30f;
#pragma unroll
        for (int j = 0; j < 10; j++) { l[j] = acc[j] + db[j]; m = fmaxf(m, l[j]); }
        float sum = 0.0f;
#pragma unroll
        for (int j = 0; j < 10; j++) { l[j] = expf(l[j] - m); sum += l[j]; }
        float inv = 1.0f / sum;
#pragma unroll
        for (int j = 0; j < 10; j++) out[warp * 10 + j] = l[j] * inv;
    }
}

// ---------------------------------------------------------------------------
// Launch. Input order: 0:x 1:w1 2:b1 3:w2 4:w3 5:w4 6:w5 7:w6
//  8..19: bn{1..6}_scale/bias interleaved, 20:dense_w 21:dense_b
// ---------------------------------------------------------------------------
extern "C" void kernel_launch(void* const* d_in, const int* in_sizes, int n_in,
                              void* d_out, int out_size) {
    const float* x   = (const float*)d_in[0];
    const float* w1  = (const float*)d_in[1];
    const float* b1  = (const float*)d_in[2];
    const float* w2  = (const float*)d_in[3];
    const float* w3  = (const float*)d_in[4];
    const float* w4  = (const float*)d_in[5];
    const float* w5  = (const float*)d_in[6];
    const float* w6  = (const float*)d_in[7];
    const float* bn1s = (const float*)d_in[8];
    const float* bn1b = (const float*)d_in[9];
    const float* bn2s = (const float*)d_in[10];
    const float* bn2b = (const float*)d_in[11];
    const float* bn3s = (const float*)d_in[12];
    const float* bn3b = (const float*)d_in[13];
    const float* bn4s = (const float*)d_in[14];
    const float* bn4b = (const float*)d_in[15];
    const float* bn5s = (const float*)d_in[16];
    const float* bn5b = (const float*)d_in[17];
    const float* bn6s = (const float*)d_in[18];
    const float* bn6b = (const float*)d_in[19];
    const float* dw   = (const float*)d_in[20];
    const float* db   = (const float*)d_in[21];
    float* out = (float*)d_out;

    uint32_t *bits1, *bits2, *bits3, *bits4, *bits5;
    uint32_t *wb2, *wb3, *wb4, *wb5, *wb6;
    int *V2, *V3, *V4, *V5, *K6A, *K6B, *part;
    float* h6;
    cudaGetSymbolAddress((void**)&bits1, g_bits1);
    cudaGetSymbolAddress((void**)&bits2, g_bits2);
    cudaGetSymbolAddress((void**)&bits3, g_bits3);
    cudaGetSymbolAddress((void**)&bits4, g_bits4);
    cudaGetSymbolAddress((void**)&bits5, g_bits5);
    cudaGetSymbolAddress((void**)&wb2, g_wb2);
    cudaGetSymbolAddress((void**)&wb3, g_wb3);
    cudaGetSymbolAddress((void**)&wb4, g_wb4);
    cudaGetSymbolAddress((void**)&wb5, g_wb5);
    cudaGetSymbolAddress((void**)&wb6, g_wb6);
    cudaGetSymbolAddress((void**)&V2, g_V2);
    cudaGetSymbolAddress((void**)&V3, g_V3);
    cudaGetSymbolAddress((void**)&V4, g_V4);
    cudaGetSymbolAddress((void**)&V5, g_V5);
    cudaGetSymbolAddress((void**)&K6A, g_K6A);
    cudaGetSymbolAddress((void**)&K6B, g_K6B);
    cudaGetSymbolAddress((void**)&part, g_part);
    cudaGetSymbolAddress((void**)&h6, g_h6);

    // 0: weight packing
    const int npack = 9 * 4 * 128 + 9 * 4 * 256 + 9 * 8 * 256 + 9 * 8 * 512 + 9 * 16 * 512;
    pack_all_kernel<<<(npack + 255) / 256, 256>>>(w2, w3, w4, w5, w6,
                                                  wb2, wb3, wb4, wb5, wb6);
    // 1: V/K tables
    const int nk = 9 * (128 + 256 + 256 + 512 + 512 + 512);
    tab_all_kernel<<<(nk + 255) / 256, 256>>>(wb2, wb3, wb4, wb5, wb6,
                                              bn2s, bn2b, bn3s, bn3b,
                                              bn4s, bn4b, bn5s, bn5b,
                                              V2, V3, V4, V5, K6A, K6B);

    // 2: conv1 + relu + bn1 + binarize   (8 pixels per block)
    conv1_kernel<<<NB * 32 * 32 / 8, 128>>>(x, w1, b1, bn1s, bn1b, bits1);

    // 3: bconv2 (128->128) + pool + bn2
    bconv_px<32, 32, 4, 4, 0, 128, true, 0><<<dim3(512, 4), 256>>>(
        bits1, wb2, V2, bn2s, bn2b, bits2, nullptr, nullptr);
    // 4: bconv3 (128->256) + bn3
    bconv_px<16, 16, 4, 4, 0, 256, false, 0><<<dim3(128, 8), 256>>>(
        bits2, wb3, V3, bn3s, bn3b, bits3, nullptr, nullptr);
    // 5: bconv4 (256->256) + pool + bn4   (profiled slot)
    bconv_px<16, 16, 8, 8, 0, 256, true, 0><<<dim3(128, 8), 256>>>(
        bits3, wb4, V4, bn4s, bn4b, bits4, nullptr, nullptr);
    // 6: bconv5 (256->512) + bn5
    bconv_px<8, 8, 8, 8, 0, 512, false, 0><<<dim3(32, 16), 256>>>(
        bits4, wb5, V5, bn5s, bn5b, bits5, nullptr, nullptr);
    // 7: bconv6 pass A (cin words 0..7) -> partial dots
    bconv_px<8, 8, 16, 8, 0, 512, false, 1><<<dim3(32, 16), 256>>>(
        bits5, wb6, K6A, bn6s, bn6b, nullptr, part, nullptr);
    // 8: bconv6 pass B (cin words 8..15) + partial + relu + pool + bn6 -> h6
    bconv_px<8, 8, 16, 8, 8, 512, true, 2><<<dim3(32, 16), 256>>>(
        bits5, wb6, K6B, bn6s, bn6b, nullptr, part, h6);

    // 9: dense + softmax
    dense_softmax_kernel<<<NB * 4 * 4 * 32 / 256, 256>>>(h6, dw, db, out);
}

// round 13
// speedup vs baseline: 2.0095x; 1.0395x over previous
#include <cuda_runtime.h>
#include <cuda_bf16.h>
#include <cstdint>
#include <math.h>

// ---------------------------------------------------------------------------
// Binarized CNN (XNOR-net) forward pass. Bit-packed XNOR-popcount convs.
// R13: ALL bconv passes use the measured-best CW=4 shape (36-reg patch,
//      ~64 regs, 44% occ): CW=8 layers split into two cin-half passes via
//      exact integer partial dots in g_part. L2 CSA (16 popc / 36 words;
//      the deeper L3 tree measured slower). Integer-threshold epilogue:
//      z = T - m exactly; bit = sign(z). conv1: 8 px/block, reg weights.
// ---------------------------------------------------------------------------

#define NB 128

// Scratch (device globals; no allocation allowed)
__device__ uint32_t g_bits1[NB * 32 * 32 * 4];
__device__ uint32_t g_bits2[NB * 16 * 16 * 4];
__device__ uint32_t g_bits3[NB * 16 * 16 * 8];
__device__ uint32_t g_bits4[NB * 8 * 8 * 8];
__device__ uint32_t g_bits5[NB * 8 * 8 * 16];
__device__ float    g_h6[NB * 4 * 4 * 512];
__device__ int      g_part[NB * 16 * 16 * 256];     // partial dots (33.5MB max)
__device__ uint32_t g_wb2[9 * 4 * 128];
__device__ uint32_t g_wb3[9 * 4 * 256];
__device__ uint32_t g_wb4[9 * 8 * 256];
__device__ uint32_t g_wb5[9 * 8 * 512];
__device__ uint32_t g_wb6[9 * 16 * 512];
// Tables (per edge pattern x cout): V = K + C0 - T (threshold), K = edge corr.
__device__ int g_V2[9 * 128];
__device__ int g_V3[9 * 256];
__device__ int g_K4A[9 * 256];
__device__ int g_V4B[9 * 256];
__device__ int g_K5A[9 * 512];
__device__ int g_V5B[9 * 512];
__device__ int g_K6A[9 * 512];
__device__ int g_K6B[9 * 512];
__device__ int g_K6C[9 * 512];
__device__ int g_K6D[9 * 512];

// ---------------------------------------------------------------------------
// Weight-sign packing. Layout per layer: [tap(9)][cin_word][cout].
// ---------------------------------------------------------------------------
__device__ __forceinline__ void pack_one(const float* __restrict__ w,
                                         uint32_t* __restrict__ wb,
                                         int idx, int CIN, int COUT) {
    int cout = idx % COUT;
    int tw = idx / COUT;
    int cw = CIN >> 5;
    int wword = tw % cw;
    int tap = tw / cw;
    uint32_t m = 0;
#pragma unroll 8
    for (int j = 0; j < 32; j++) {
        float f = w[(tap * CIN + wword * 32 + j) * COUT + cout];
        m |= (f > 0.0f ? 1u : 0u) << j;
    }
    wb[idx] = m;
}

__global__ void pack_all_kernel(const float* __restrict__ w2, const float* __restrict__ w3,
                                const float* __restrict__ w4, const float* __restrict__ w5,
                                const float* __restrict__ w6,
                                uint32_t* __restrict__ wb2, uint32_t* __restrict__ wb3,
                                uint32_t* __restrict__ wb4, uint32_t* __restrict__ wb5,
                                uint32_t* __restrict__ wb6) {
    int idx = blockIdx.x * blockDim.x + threadIdx.x;
    const int n2 = 9 * 4 * 128, n3 = 9 * 4 * 256, n4 = 9 * 8 * 256,
              n5 = 9 * 8 * 512, n6 = 9 * 16 * 512;
    if (idx < n2) { pack_one(w2, wb2, idx, 128, 128); return; }
    idx -= n2;
    if (idx < n3) { pack_one(w3, wb3, idx, 128, 256); return; }
    idx -= n3;
    if (idx < n4) { pack_one(w4, wb4, idx, 256, 256); return; }
    idx -= n4;
    if (idx < n5) { pack_one(w5, wb5, idx, 256, 512); return; }
    idx -= n5;
    if (idx < n6) { pack_one(w6, wb6, idx, 512, 512); return; }
}

// ---------------------------------------------------------------------------
// K = (valid - 9)*CW*32 + 2 * sum_{invalid taps} popc(w_chunk)
// so that dot_true = C0 - 2*S_zeropadded + K, C0 = 9*CW*32.
// ---------------------------------------------------------------------------
__device__ __forceinline__ int k_compute(const uint32_t* __restrict__ wb,
                                         int c, int p, int CINW, int CW, int w0, int COUT) {
    int ty = p / 3, tx = p % 3;
    int sinv = 0, valid = 0;
    for (int ky = 0; ky < 3; ky++) {
        for (int kx = 0; kx < 3; kx++) {
            bool inv = (ty == 0 && ky == 0) || (ty == 2 && ky == 2) ||
                       (tx == 0 && kx == 0) || (tx == 2 && kx == 2);
            if (!inv) { valid++; continue; }
            for (int w = 0; w < CW; w++)
                sinv += __popc(wb[((size_t)(ky * 3 + kx) * CINW + w0 + w) * COUT + c]);
        }
    }
    return (valid - 9) * CW * 32 + 2 * sinv;
}

// V = K + C0 - T; T = max{ m : fmaf(m,sc,bi) <= 0 } (exact, same fmaf as the
// runtime predicate). bias>0 => relu makes the bit always 1 => big sentinel
// (all |z| quantities < 1e4, so 1e5 guarantees z<0).
__device__ __forceinline__ void v_one(const uint32_t* __restrict__ wb, int* __restrict__ V,
                                      int idx, int CINW, int CW, int w0, int COUT,
                                      const float* __restrict__ scale,
                                      const float* __restrict__ bias) {
    int c = idx % COUT;
    int p = idx / COUT;
    int K = k_compute(wb, c, p, CINW, CW, w0, COUT);
    const int C0 = 9 * CW * 32;
    float sc = scale[c], bi = bias[c];
    int v;
    if (bi > 0.0f) {
        v = 100000;
    } else {
        float t0 = -bi / sc;
        int T = (int)floorf(t0);
        while (fmaf((float)(T + 1), sc, bi) <= 0.0f) T++;
        while (fmaf((float)T, sc, bi) > 0.0f) T--;
        v = K + C0 - T;
    }
    V[idx] = v;
}

__device__ __forceinline__ void k_one(const uint32_t* __restrict__ wb, int* __restrict__ K,
                                      int idx, int CINW, int CW, int w0, int COUT) {
    int c = idx % COUT;
    int p = idx / COUT;
    K[idx] = k_compute(wb, c, p, CINW, CW, w0, COUT);
}

__global__ void tab_all_kernel(const uint32_t* __restrict__ wb2, const uint32_t* __restrict__ wb3,
                               const uint32_t* __restrict__ wb4, const uint32_t* __restrict__ wb5,
                               const uint32_t* __restrict__ wb6,
                               const float* s2, const float* b2, const float* s3, const float* b3,
                               const float* s4, const float* b4, const float* s5, const float* b5,
                               int* V2, int* V3, int* K4A, int* V4B, int* K5A, int* V5B,
                               int* K6A, int* K6B, int* K6C, int* K6D) {
    int idx = blockIdx.x * blockDim.x + threadIdx.x;
    const int t128 = 9 * 128, t256 = 9 * 256, t512 = 9 * 512;
    if (idx < t128) { v_one(wb2, V2, idx, 4, 4, 0, 128, s2, b2); return; }
    idx -= t128;
    if (idx < t256) { v_one(wb3, V3, idx, 4, 4, 0, 256, s3, b3); return; }
    idx -= t256;
    if (idx < t256) { k_one(wb4, K4A, idx, 8, 4, 0, 256); return; }
    idx -= t256;
    if (idx < t256) { v_one(wb4, V4B, idx, 8, 4, 4, 256, s4, b4); return; }
    idx -= t256;
    if (idx < t512) { k_one(wb5, K5A, idx, 8, 4, 0, 512); return; }
    idx -= t512;
    if (idx < t512) { v_one(wb5, V5B, idx, 8, 4, 4, 512, s5, b5); return; }
    idx -= t512;
    if (idx < t512) { k_one(wb6, K6A, idx, 16, 4, 0, 512); return; }
    idx -= t512;
    if (idx < t512) { k_one(wb6, K6B, idx, 16, 4, 4, 512); return; }
    idx -= t512;
    if (idx < t512) { k_one(wb6, K6C, idx, 16, 4, 8, 512); return; }
    idx -= t512;
    if (idx < t512) { k_one(wb6, K6D, idx, 16, 4, 12, 512); return; }
}

// ---------------------------------------------------------------------------
// conv1: float 3x3 SAME conv (3->128) + bias + relu + bn + binarize + pack.
// 8 consecutive pixels per block; 27 weights register-resident.
// ---------------------------------------------------------------------------
__global__ void __launch_bounds__(128) conv1_kernel(
    const float* __restrict__ x, const float* __restrict__ w1,
    const float* __restrict__ b1, const float* __restrict__ s1,
    const float* __restrict__ bb1, uint32_t* __restrict__ obits) {
    constexpr int PIX = 8;
    const int co = threadIdx.x;

    float wreg[27];
#pragma unroll
    for (int t = 0; t < 27; t++) wreg[t] = __ldg(w1 + t * 128 + co);
    const float bb = __ldg(b1 + co);
    const float sc = __ldg(s1 + co);
    const float bi = __ldg(bb1 + co);

    const int p0 = blockIdx.x * PIX;        // 8 consecutive x in one row
    const int y = (p0 >> 5) & 31;
    const int n = p0 >> 10;
    const int x0 = p0 & 31;

#pragma unroll 1
    for (int pp = 0; pp < PIX; pp++) {
        int xx = x0 + pp;
        float acc = 0.0f;
#pragma unroll
        for (int ky = 0; ky < 3; ky++) {
            int iy = y + ky - 1;
            if ((unsigned)iy >= 32u) continue;
#pragma unroll
            for (int kx = 0; kx < 3; kx++) {
                int ix = xx + kx - 1;
                if ((unsigned)ix >= 32u) continue;
                const float* xp = x + ((n * 32 + iy) * 32 + ix) * 3;
                const float* wr = wreg + (ky * 3 + kx) * 3;
                acc = fmaf(xp[0], wr[0], acc);
                acc = fmaf(xp[1], wr[1], acc);
                acc = fmaf(xp[2], wr[2], acc);
            }
        }
        float v = fmaxf(acc + bb, 0.0f);
        v = fmaf(v, sc, bi);
        unsigned mask = __ballot_sync(0xffffffffu, v > 0.0f);
        if ((co & 31) == 0) obits[(p0 + pp) * 4 + (co >> 5)] = mask;
    }
}

// Full adder (carry-save): s = xor3 (LOP3 0x96), c = majority (LOP3 0xE8).
__device__ __forceinline__ void csa(uint32_t a, uint32_t b, uint32_t d,
                                    uint32_t& s, uint32_t& c) {
    s = a ^ b ^ d;
    c = (a & b) | (d & (a ^ b));
}

// ---------------------------------------------------------------------------
// Binary conv, lane = pixel, L2-CSA popcount (16 POPCs / 36 words).
//   CW = 4 always (36-word block). W0 selects the cin-half/quarter.
//   MODE 0: z = 2s - V -> (pool min) -> sign bit -> word   (tab = V)
//   MODE 1: part  = C0 - 2s + K                            (tab = K)
//   MODE 2: m = C0 - 2s + K + part; relu; pool; bn -> float (tab = K)
//   MODE 3: z = 2s - V - part -> (pool min) -> sign bit    (tab = V-half)
//   MODE 4: part += C0 - 2s + K                            (tab = K)
// Warp strip: RS rows x CS cols (CS = min(W,16), RS = 32/CS).
// Grid: x = (NB*H*W/32)/8 blocks of 8 warps, y = COUT/32.
// ---------------------------------------------------------------------------
template <int H, int W, int CINW, int W0, int COUT, bool POOL, int MODE>
__global__ void __launch_bounds__(256) bconv_px(
    const uint32_t* __restrict__ abits, const uint32_t* __restrict__ wbits,
    const int* __restrict__ tab, const float* __restrict__ scale,
    const float* __restrict__ bias, uint32_t* __restrict__ obits,
    int* __restrict__ part, float* __restrict__ ofloat) {
    constexpr int NT = 256;
    constexpr int CW = 4;
    constexpr int CS = (W < 16) ? W : 16;
    constexpr int RS = 32 / CS;
    constexpr int SPI = (H * W) / 32;       // strips per image
    constexpr int WCS = W / CS;             // col-strips per row-group
    constexpr int TPW = 9;                  // uint4 per cout (9 taps x 1)
    constexpr int NPIX = NB * H * W;
    constexpr int C0 = 9 * CW * 32;

    __shared__ uint4 sw4[32 * TPW];
    __shared__ int sk[9 * 33];
    __shared__ float ssc[32], sbi[32];

    const int g = blockIdx.y;
    {
        uint32_t* sws = (uint32_t*)sw4;
        for (int idx = threadIdx.x; idx < 32 * 9 * CW; idx += NT) {
            int c = idx / (9 * CW);
            int t = idx - c * (9 * CW);
            int tap = t / CW, w = t - tap * CW;
            sws[idx] = wbits[((size_t)tap * CINW + W0 + w) * COUT + g * 32 + c];
        }
        for (int idx = threadIdx.x; idx < 9 * 32; idx += NT) {
            int p = idx >> 5, c = idx & 31;
            sk[p * 33 + c] = tab[p * COUT + g * 32 + c];
        }
        if (threadIdx.x < 32) {
            ssc[threadIdx.x] = scale[g * 32 + threadIdx.x];
            sbi[threadIdx.x] = bias[g * 32 + threadIdx.x];
        }
    }
    __syncthreads();

    const int lane = threadIdx.x & 31;
    const int warp = threadIdx.x >> 5;
    const int sid = blockIdx.x * 8 + warp;
    const int n = sid / SPI;
    const int si = sid - n * SPI;
    const int rowg = si / WCS;
    const int colg = si - rowg * WCS;
    const int r = lane / CS;
    const int x = lane - r * CS;
    const int py = rowg * RS + r;
    const int px = colg * CS + x;

    // Activation patch (zero-filled outside the image)
    uint4 patch[TPW];
#pragma unroll
    for (int ky = 0; ky < 3; ky++) {
#pragma unroll
        for (int kx = 0; kx < 3; kx++) {
            int iy = py + ky - 1, ix = px + kx - 1;
            bool ok = ((unsigned)iy < (unsigned)H) && ((unsigned)ix < (unsigned)W);
            uint4 a = make_uint4(0u, 0u, 0u, 0u);
            if (ok) a = __ldg((const uint4*)(abits +
                    ((size_t)(n * H + iy) * W + ix) * CINW + W0));
            patch[ky * 3 + kx] = a;
        }
    }

    const int ty = (py == 0) ? 0 : ((py == H - 1) ? 2 : 1);
    const int txp = (px == 0) ? 0 : ((px == W - 1) ? 2 : 1);
    const int pat = ty * 3 + txp;
    const int gpix = (n * H + py) * W + px;

    uint32_t word = 0;
#pragma unroll 1
    for (int c = 31; c >= 0; c--) {
        const uint4* wr = &sw4[c * TPW];
        const int dv = sk[pat * 33 + c];
        // XOR 36 words
        uint32_t xw[36];
#pragma unroll
        for (int t = 0; t < 9; t++) {
            uint4 wv = wr[t];              // warp-uniform -> LDS broadcast
            uint4 av = patch[t];
            xw[t * 4 + 0] = av.x ^ wv.x;
            xw[t * 4 + 1] = av.y ^ wv.y;
            xw[t * 4 + 2] = av.z ^ wv.z;
            xw[t * 4 + 3] = av.w ^ wv.w;
        }
        // L1: 36 -> 12 s1 (wt1) + 12 c1 (wt2)
        uint32_t s1[12], c1[12];
#pragma unroll
        for (int i = 0; i < 12; i++)
            csa(xw[3 * i], xw[3 * i + 1], xw[3 * i + 2], s1[i], c1[i]);
        // L2: 12 wt1 -> 4+4; 12 wt2 -> 4+4
        uint32_t s2[4], c2[4], t2[4], d4[4];
#pragma unroll
        for (int i = 0; i < 4; i++)
            csa(s1[3 * i], s1[3 * i + 1], s1[3 * i + 2], s2[i], c2[i]);
#pragma unroll
        for (int i = 0; i < 4; i++)
            csa(c1[3 * i], c1[3 * i + 1], c1[3 * i + 2], t2[i], d4[i]);
        int A = __popc(s2[0]) + __popc(s2[1]) + __popc(s2[2]) + __popc(s2[3]);
        int B = __popc(c2[0]) + __popc(c2[1]) + __popc(c2[2]) + __popc(c2[3]) +
                __popc(t2[0]) + __popc(t2[1]) + __popc(t2[2]) + __popc(t2[3]);
        int C = __popc(d4[0]) + __popc(d4[1]) + __popc(d4[2]) + __popc(d4[3]);
        int s = A + 2 * (B + 2 * C);       // exact popcount sum of the 36 words

        if constexpr (MODE == 0) {
            int z = 2 * s - dv;            // z = T - dot
            if constexpr (POOL) {
                z = min(z, __shfl_xor_sync(0xffffffffu, z, 1));
                z = min(z, __shfl_xor_sync(0xffffffffu, z, CS));
            }
            word = (word << 1) | ((uint32_t)z >> 31);
        } else if constexpr (MODE == 1) {
            part[(size_t)(g * 32 + c) * NPIX + gpix] = C0 - 2 * s + dv;
        } else if constexpr (MODE == 3) {
            int z = 2 * s - dv - __ldg(part + (size_t)(g * 32 + c) * NPIX + gpix);
            if constexpr (POOL) {
                z = min(z, __shfl_xor_sync(0xffffffffu, z, 1));
                z = min(z, __shfl_xor_sync(0xffffffffu, z, CS));
            }
            word = (word << 1) | ((uint32_t)z >> 31);
        } else if constexpr (MODE == 4) {
            size_t pi = (size_t)(g * 32 + c) * NPIX + gpix;
            part[pi] = part[pi] + (C0 - 2 * s + dv);
        } else {                            // MODE 2: final float
            int m = C0 - 2 * s + dv + __ldg(part + (size_t)(g * 32 + c) * NPIX + gpix);
            m = max(m, 0);                 // relu (before pool is exact)
            if constexpr (POOL) {
                m = max(m, __shfl_xor_sync(0xffffffffu, m, 1));
                m = max(m, __shfl_xor_sync(0xffffffffu, m, CS));
            }
            float v = fmaf((float)m, ssc[c], sbi[c]);
            if (((r & 1) == 0) && ((x & 1) == 0)) {
                int opix = (n * (H / 2) + (py >> 1)) * (W / 2) + (px >> 1);
                ofloat[(size_t)opix * COUT + g * 32 + c] = v;
            }
        }
    }

    if constexpr (MODE == 0 || MODE == 3) {
        if constexpr (POOL) {
            if (((r & 1) == 0) && ((x & 1) == 0)) {
                int opix = (n * (H / 2) + (py >> 1)) * (W / 2) + (px >> 1);
                obits[(size_t)opix * (COUT / 32) + g] = word;
            }
        } else {
            obits[(size_t)gpix * (COUT / 32) + g] = word;
        }
    }
}

// ---------------------------------------------------------------------------
// Dense (512->10) + softmax, one warp per output pixel.
// ---------------------------------------------------------------------------
__global__ void dense_softmax_kernel(const float* __restrict__ h, const float* __restrict__ dw,
                                     const float* __restrict__ db, float* __restrict__ out) {
    int warp = (blockIdx.x * blockDim.x + threadIdx.x) >> 5;
    int lane = threadIdx.x & 31;
    if (warp >= NB * 4 * 4) return;
    float acc[10];
#pragma unroll
    for (int j = 0; j < 10; j++) acc[j] = 0.0f;
    const float* hp = h + (size_t)warp * 512;
#pragma unroll
    for (int k = 0; k < 16; k++) {
        int cc = k * 32 + lane;
        float hv = hp[cc];
        const float* wp = dw + cc * 10;
#pragma unroll
        for (int j = 0; j < 10; j++) acc[j] = fmaf(hv, __ldg(wp + j), acc[j]);
    }
#pragma unroll
    for (int s = 16; s > 0; s >>= 1) {
#pragma unroll
        for (int j = 0; j < 10; j++) acc[j] += __shfl_xor_sync(0xffffffffu, acc[j], s);
    }
    if (lane == 0) {
        float l[10], m = -1e30f;
#pragma unroll
        for (int j = 0; j < 10; j++) { l[j] = acc[j] + db[j]; m = fmaxf(m, l[j]); }
        float sum = 0.0f;
#pragma unroll
        for (int j = 0; j < 10; j++) { l[j] = expf(l[j] - m); sum += l[j]; }
        float inv = 1.0f / sum;
#pragma unroll
        for (int j = 0; j < 10; j++) out[warp * 10 + j] = l[j] * inv;
    }
}

// ---------------------------------------------------------------------------
// Launch. Input order: 0:x 1:w1 2:b1 3:w2 4:w3 5:w4 6:w5 7:w6
//  8..19: bn{1..6}_scale/bias interleaved, 20:dense_w 21:dense_b
// ---------------------------------------------------------------------------
extern "C" void kernel_launch(void* const* d_in, const int* in_sizes, int n_in,
                              void* d_out, int out_size) {
    const float* x   = (const float*)d_in[0];
    const float* w1  = (const float*)d_in[1];
    const float* b1  = (const float*)d_in[2];
    const float* w2  = (const float*)d_in[3];
    const float* w3  = (const float*)d_in[4];
    const float* w4  = (const float*)d_in[5];
    const float* w5  = (const float*)d_in[6];
    const float* w6  = (const float*)d_in[7];
    const float* bn1s = (const float*)d_in[8];
    const float* bn1b = (const float*)d_in[9];
    const float* bn2s = (const float*)d_in[10];
    const float* bn2b = (const float*)d_in[11];
    const float* bn3s = (const float*)d_in[12];
    const float* bn3b = (const float*)d_in[13];
    const float* bn4s = (const float*)d_in[14];
    const float* bn4b = (const float*)d_in[15];
    const float* bn5s = (const float*)d_in[16];
    const float* bn5b = (const float*)d_in[17];
    const float* bn6s = (const float*)d_in[18];
    const float* bn6b = (const float*)d_in[19];
    const float* dw   = (const float*)d_in[20];
    const float* db   = (const float*)d_in[21];
    float* out = (float*)d_out;

    uint32_t *bits1, *bits2, *bits3, *bits4, *bits5;
    uint32_t *wb2, *wb3, *wb4, *wb5, *wb6;
    int *V2, *V3, *K4A, *V4B, *K5A, *V5B, *K6A, *K6B, *K6C, *K6D, *part;
    float* h6;
    cudaGetSymbolAddress((void**)&bits1, g_bits1);
    cudaGetSymbolAddress((void**)&bits2, g_bits2);
    cudaGetSymbolAddress((void**)&bits3, g_bits3);
    cudaGetSymbolAddress((void**)&bits4, g_bits4);
    cudaGetSymbolAddress((void**)&bits5, g_bits5);
    cudaGetSymbolAddress((void**)&wb2, g_wb2);
    cudaGetSymbolAddress((void**)&wb3, g_wb3);
    cudaGetSymbolAddress((void**)&wb4, g_wb4);
    cudaGetSymbolAddress((void**)&wb5, g_wb5);
    cudaGetSymbolAddress((void**)&wb6, g_wb6);
    cudaGetSymbolAddress((void**)&V2, g_V2);
    cudaGetSymbolAddress((void**)&V3, g_V3);
    cudaGetSymbolAddress((void**)&K4A, g_K4A);
    cudaGetSymbolAddress((void**)&V4B, g_V4B);
    cudaGetSymbolAddress((void**)&K5A, g_K5A);
    cudaGetSymbolAddress((void**)&V5B, g_V5B);
    cudaGetSymbolAddress((void**)&K6A, g_K6A);
    cudaGetSymbolAddress((void**)&K6B, g_K6B);
    cudaGetSymbolAddress((void**)&K6C, g_K6C);
    cudaGetSymbolAddress((void**)&K6D, g_K6D);
    cudaGetSymbolAddress((void**)&part, g_part);
    cudaGetSymbolAddress((void**)&h6, g_h6);

    // 0: weight packing
    const int npack = 9 * 4 * 128 + 9 * 4 * 256 + 9 * 8 * 256 + 9 * 8 * 512 + 9 * 16 * 512;
    pack_all_kernel<<<(npack + 255) / 256, 256>>>(w2, w3, w4, w5, w6,
                                                  wb2, wb3, wb4, wb5, wb6);
    // 1: V/K tables
    const int nk = 9 * (128 + 256 * 3 + 512 * 6);
    tab_all_kernel<<<(nk + 255) / 256, 256>>>(wb2, wb3, wb4, wb5, wb6,
                                              bn2s, bn2b, bn3s, bn3b,
                                              bn4s, bn4b, bn5s, bn5b,
                                              V2, V3, K4A, V4B, K5A, V5B,
                                              K6A, K6B, K6C, K6D);

    // 2: conv1 + relu + bn1 + binarize   (8 pixels per block)
    conv1_kernel<<<NB * 32 * 32 / 8, 128>>>(x, w1, b1, bn1s, bn1b, bits1);

    // 3: bconv2 (128->128) + pool + bn2
    bconv_px<32, 32, 4, 0, 128, true, 0><<<dim3(512, 4), 256>>>(
        bits1, wb2, V2, bn2s, bn2b, bits2, nullptr, nullptr);
    // 4: bconv3 (128->256) + bn3
    bconv_px<16, 16, 4, 0, 256, false, 0><<<dim3(128, 8), 256>>>(
        bits2, wb3, V3, bn3s, bn3b, bits3, nullptr, nullptr);
    // 5-6: bconv4 (256->256) + pool + bn4, split into 2 cin-halves
    bconv_px<16, 16, 8, 0, 256, false, 1><<<dim3(128, 8), 256>>>(
        bits3, wb4, K4A, bn4s, bn4b, nullptr, part, nullptr);
    bconv_px<16, 16, 8, 4, 256, true, 3><<<dim3(128, 8), 256>>>(
        bits3, wb4, V4B, bn4s, bn4b, bits4, part, nullptr);
    // 7-8: bconv5 (256->512) + bn5, split into 2 cin-halves
    bconv_px<8, 8, 8, 0, 512, false, 1><<<dim3(32, 16), 256>>>(
        bits4, wb5, K5A, bn5s, bn5b, nullptr, part, nullptr);
    bconv_px<8, 8, 8, 4, 512, false, 3><<<dim3(32, 16), 256>>>(
        bits4, wb5, V5B, bn5s, bn5b, bits5, part, nullptr);
    // 9-12: bconv6 (512->512) + pool + bn6 -> float, 4 cin-quarters
    bconv_px<8, 8, 16, 0, 512, false, 1><<<dim3(32, 16), 256>>>(
        bits5, wb6, K6A, bn6s, bn6b, nullptr, part, nullptr);
    bconv_px<8, 8, 16, 4, 512, false, 4><<<dim3(32, 16), 256>>>(
        bits5, wb6, K6B, bn6s, bn6b, nullptr, part, nullptr);
    bconv_px<8, 8, 16, 8, 512, false, 4><<<dim3(32, 16), 256>>>(
        bits5, wb6, K6C, bn6s, bn6b, nullptr, part, nullptr);
    bconv_px<8, 8, 16, 12, 512, true, 2><<<dim3(32, 16), 256>>>(
        bits5, wb6, K6D, bn6s, bn6b, nullptr, part, h6);

    // 13: dense + softmax
    dense_softmax_kernel<<<NB * 4 * 4 * 32 / 256, 256>>>(h6, dw, db, out);
}